// round 2
// baseline (speedup 1.0000x reference)
#include <cuda_runtime.h>
#include <cstdint>

#define Bn   16
#define Cn   256
#define Tn   1024
#define KEYn 256
#define INV_SQRT_K 0.0625f

// ---------------- scratch (device globals; no allocation allowed) ----------
__device__ float g_q[Bn * Tn * KEYn];
__device__ float g_k[Bn * Tn * KEYn];
__device__ float g_v[Bn * Tn * Cn];
__device__ float g_attn[(size_t)Bn * Tn * Tn];   // exp(scores), unnormalized
__device__ float g_colpart[(size_t)8 * Bn * Tn]; // per-j-tile column partial sums
__device__ float g_invcol[Bn * Tn];              // 1 / column sum
__device__ float g_rowsum[Bn * Tn];
__device__ float g_wx[Bn * Tn];
__device__ float g_oa[Bn * Cn * Tn];             // attention output, [B,C,T]
__device__ float g_h1[Bn * Cn * Tn];             // conv1 output
__device__ float g_w1[Cn * Cn * 3];              // weight-normed conv weights
__device__ float g_w2[Cn * Cn * 3];

// ---------------- weight norm: w = g * v / ||v||_(in,k) --------------------
__global__ __launch_bounds__(256) void wnorm_kernel(const float* __restrict__ v,
                                                    const float* __restrict__ g,
                                                    int which) {
    float* w = which ? g_w2 : g_w1;
    int o = blockIdx.x;
    int tid = threadIdx.x;
    __shared__ float red[256];
    float s = 0.f;
    for (int i = tid; i < Cn * 3; i += 256) {
        float t = v[o * Cn * 3 + i];
        s += t * t;
    }
    red[tid] = s;
    __syncthreads();
    for (int st = 128; st > 0; st >>= 1) {
        if (tid < st) red[tid] += red[tid + st];
        __syncthreads();
    }
    float scale = g[o] * rsqrtf(red[0]);
    for (int i = tid; i < Cn * 3; i += 256)
        w[o * Cn * 3 + i] = v[o * Cn * 3 + i] * scale;
}

// ---------------- q/k/v GEMM: out[b,t,n] = sum_c x[b,c,t]*W[c,n] + bias ----
// 128x128 tile, 8x8 microtile, which: 0->q 1->k 2->v
__global__ __launch_bounds__(256) void gemm_qkv(const float* __restrict__ x,
                                                const float* __restrict__ W,
                                                const float* __restrict__ bias,
                                                int which) {
    float* out = (which == 0) ? g_q : (which == 1) ? g_k : g_v;
    __shared__ float As[16][128];   // [c_k][t]
    __shared__ float Bs[16][128];   // [c_k][n]
    int b = blockIdx.z;
    int t0 = blockIdx.x * 128, n0 = blockIdx.y * 128;
    int tid = threadIdx.x;
    int tx = tid & 15, ty = tid >> 4;
    int lr = tid >> 5, lc = (tid & 31) * 4;
    const float* xb = x + (size_t)b * Cn * Tn;
    float acc[8][8] = {};
    for (int c0 = 0; c0 < Cn; c0 += 16) {
        *(float4*)&As[lr][lc]     = *(const float4*)&xb[(c0 + lr) * Tn + t0 + lc];
        *(float4*)&As[lr + 8][lc] = *(const float4*)&xb[(c0 + lr + 8) * Tn + t0 + lc];
        *(float4*)&Bs[lr][lc]     = *(const float4*)&W[(c0 + lr) * 256 + n0 + lc];
        *(float4*)&Bs[lr + 8][lc] = *(const float4*)&W[(c0 + lr + 8) * 256 + n0 + lc];
        __syncthreads();
#pragma unroll
        for (int kk = 0; kk < 16; kk++) {
            float4 a0 = *(float4*)&As[kk][ty * 8], a1 = *(float4*)&As[kk][ty * 8 + 4];
            float4 b0 = *(float4*)&Bs[kk][tx * 8], b1 = *(float4*)&Bs[kk][tx * 8 + 4];
            float av[8] = {a0.x, a0.y, a0.z, a0.w, a1.x, a1.y, a1.z, a1.w};
            float bv[8] = {b0.x, b0.y, b0.z, b0.w, b1.x, b1.y, b1.z, b1.w};
#pragma unroll
            for (int i = 0; i < 8; i++)
#pragma unroll
                for (int j = 0; j < 8; j++) acc[i][j] += av[i] * bv[j];
        }
        __syncthreads();
    }
    float4 bb0 = *(const float4*)&bias[n0 + tx * 8];
    float4 bb1 = *(const float4*)&bias[n0 + tx * 8 + 4];
    float bvv[8] = {bb0.x, bb0.y, bb0.z, bb0.w, bb1.x, bb1.y, bb1.z, bb1.w};
#pragma unroll
    for (int i = 0; i < 8; i++) {
        int t = t0 + ty * 8 + i;
        float* orow = &out[((size_t)b * Tn + t) * 256 + n0 + tx * 8];
        *(float4*)&orow[0] = make_float4(acc[i][0] + bvv[0], acc[i][1] + bvv[1],
                                         acc[i][2] + bvv[2], acc[i][3] + bvv[3]);
        *(float4*)&orow[4] = make_float4(acc[i][4] + bvv[4], acc[i][5] + bvv[5],
                                         acc[i][6] + bvv[6], acc[i][7] + bvv[7]);
    }
}

// ------------- scores: e[b,j,i] = (i<=j) ? exp(q[b,j]·k[b,i]/16) : 0 -------
// Writes unnormalized exp values + deterministic column partial sums.
__global__ __launch_bounds__(256) void gemm_scores() {
    int b = blockIdx.z;
    int i0 = blockIdx.x * 128, j0 = blockIdx.y * 128;
    int tid = threadIdx.x;
    int tx = tid & 15, ty = tid >> 4;
    float* S = g_attn + (size_t)b * Tn * Tn;
    float* cpart = g_colpart + (size_t)(j0 >> 7) * Bn * Tn + b * Tn + i0;
    if (i0 > j0) {  // fully masked tile: exp = 0, no column contribution
        float4 z = make_float4(0.f, 0.f, 0.f, 0.f);
#pragma unroll
        for (int i = 0; i < 8; i++) {
            int j = j0 + ty * 8 + i;
            *(float4*)&S[(size_t)j * Tn + i0 + tx * 8] = z;
            *(float4*)&S[(size_t)j * Tn + i0 + tx * 8 + 4] = z;
        }
        if (tid < 128) cpart[tid] = 0.f;
        return;
    }
    __shared__ float Qs[16][132];   // [k][j]  (transposed on load)
    __shared__ float Ks[16][132];   // [k][i]
    __shared__ float cred[16][128];
    int lj = tid >> 2, lv = (tid & 3) * 4;
    const float* qb = g_q + (size_t)b * Tn * KEYn;
    const float* kb = g_k + (size_t)b * Tn * KEYn;
    float acc[8][8] = {};
    for (int kc = 0; kc < KEYn; kc += 16) {
#pragma unroll
        for (int r = 0; r < 128; r += 64) {
            float4 qv = *(const float4*)&qb[(size_t)(j0 + lj + r) * 256 + kc + lv];
            Qs[lv + 0][lj + r] = qv.x; Qs[lv + 1][lj + r] = qv.y;
            Qs[lv + 2][lj + r] = qv.z; Qs[lv + 3][lj + r] = qv.w;
            float4 kv = *(const float4*)&kb[(size_t)(i0 + lj + r) * 256 + kc + lv];
            Ks[lv + 0][lj + r] = kv.x; Ks[lv + 1][lj + r] = kv.y;
            Ks[lv + 2][lj + r] = kv.z; Ks[lv + 3][lj + r] = kv.w;
        }
        __syncthreads();
#pragma unroll
        for (int kk = 0; kk < 16; kk++) {
            float4 a0 = *(float4*)&Qs[kk][ty * 8], a1 = *(float4*)&Qs[kk][ty * 8 + 4];
            float4 b0 = *(float4*)&Ks[kk][tx * 8], b1 = *(float4*)&Ks[kk][tx * 8 + 4];
            float av[8] = {a0.x, a0.y, a0.z, a0.w, a1.x, a1.y, a1.z, a1.w};
            float bv[8] = {b0.x, b0.y, b0.z, b0.w, b1.x, b1.y, b1.z, b1.w};
#pragma unroll
            for (int i = 0; i < 8; i++)
#pragma unroll
                for (int j = 0; j < 8; j++) acc[i][j] += av[i] * bv[j];
        }
        __syncthreads();
    }
    float csum[8] = {};
#pragma unroll
    for (int r = 0; r < 8; r++) {
        int j = j0 + ty * 8 + r;
        float e[8];
#pragma unroll
        for (int c = 0; c < 8; c++) {
            int i = i0 + tx * 8 + c;
            e[c] = (i <= j) ? __expf(acc[r][c] * INV_SQRT_K) : 0.f;
            csum[c] += e[c];
        }
        float* srow = &S[(size_t)j * Tn + i0 + tx * 8];
        *(float4*)&srow[0] = make_float4(e[0], e[1], e[2], e[3]);
        *(float4*)&srow[4] = make_float4(e[4], e[5], e[6], e[7]);
    }
#pragma unroll
    for (int c = 0; c < 8; c++) cred[ty][tx * 8 + c] = csum[c];
    __syncthreads();
    if (tid < 128) {
        float s = 0.f;
#pragma unroll
        for (int k = 0; k < 16; k++) s += cred[k][tid];
        cpart[tid] = s;
    }
}

// ------------- invcol[b,i] = 1 / sum_p colpart[p][b,i] ---------------------
__global__ __launch_bounds__(256) void invcol_kernel() {
    int idx = blockIdx.x * 256 + threadIdx.x;
    float s = 0.f;
#pragma unroll
    for (int p = 0; p < 8; p++) s += g_colpart[(size_t)p * Bn * Tn + idx];
    g_invcol[idx] = 1.f / s;
}

// ------------- rowsum[b,j] = sum_i e[b,j,i] * invcol[b,i] ------------------
__global__ __launch_bounds__(256) void row_sum() {
    int b = blockIdx.y;
    int j = blockIdx.x * 8 + (threadIdx.x >> 5);
    int lane = threadIdx.x & 31;
    const float* row = g_attn + (size_t)b * Tn * Tn + (size_t)j * Tn;
    const float* inv = g_invcol + b * Tn;
    float s = 0.f;
    for (int i = lane; i < Tn; i += 32) s += row[i] * inv[i];
#pragma unroll
    for (int o = 16; o > 0; o >>= 1) s += __shfl_xor_sync(0xffffffffu, s, o);
    if (lane == 0) g_rowsum[b * Tn + j] = s;
}

// ------------- weight_x[b,:] = softmax_j(rowsum[b,:]) ----------------------
__global__ __launch_bounds__(256) void wx_softmax() {
    int b = blockIdx.x;
    int tid = threadIdx.x;
    __shared__ float red[256];
    const float* r = g_rowsum + b * Tn;
    float m = -1e30f;
    for (int j = tid; j < Tn; j += 256) m = fmaxf(m, r[j]);
    red[tid] = m;
    __syncthreads();
    for (int st = 128; st > 0; st >>= 1) {
        if (tid < st) red[tid] = fmaxf(red[tid], red[tid + st]);
        __syncthreads();
    }
    m = red[0];
    __syncthreads();
    float sum = 0.f;
    for (int j = tid; j < Tn; j += 256) sum += __expf(r[j] - m);
    red[tid] = sum;
    __syncthreads();
    for (int st = 128; st > 0; st >>= 1) {
        if (tid < st) red[tid] += red[tid + st];
        __syncthreads();
    }
    float inv = 1.f / red[0];
    for (int j = tid; j < Tn; j += 256)
        g_wx[b * Tn + j] = __expf(r[j] - m) * inv;
}

// ------------- out_attn[b,c,j] = sum_i e[b,j,i]*invcol[i] * v[b,i,c] -------
// normalization folded into the V tile load (per-i scale).
__global__ __launch_bounds__(256) void gemm_av() {
    int b = blockIdx.z;
    int j0 = blockIdx.x * 128, c0 = blockIdx.y * 128;
    int tid = threadIdx.x;
    int tx = tid & 15, ty = tid >> 4;
    __shared__ float As[16][132];   // [i_k][j] transposed exp-weights
    __shared__ float Bs[16][128];   // [i_k][c] scaled V rows
    const float* A = g_attn + (size_t)b * Tn * Tn;
    const float* V = g_v + (size_t)b * Tn * Cn;
    const float* inv = g_invcol + b * Tn;
    int lj = tid >> 2, lv = (tid & 3) * 4;
    int lr = tid >> 5, lc = (tid & 31) * 4;
    float acc[8][8] = {};
    int kend = j0 + 128;   // causal: e[j,i]==0 for i>j
    for (int ii = 0; ii < kend; ii += 16) {
#pragma unroll
        for (int r = 0; r < 128; r += 64) {
            float4 av = *(const float4*)&A[(size_t)(j0 + lj + r) * Tn + ii + lv];
            As[lv + 0][lj + r] = av.x; As[lv + 1][lj + r] = av.y;
            As[lv + 2][lj + r] = av.z; As[lv + 3][lj + r] = av.w;
        }
        float s0 = inv[ii + lr], s1 = inv[ii + lr + 8];
        float4 v0 = *(const float4*)&V[(size_t)(ii + lr) * 256 + c0 + lc];
        float4 v1 = *(const float4*)&V[(size_t)(ii + lr + 8) * 256 + c0 + lc];
        *(float4*)&Bs[lr][lc]     = make_float4(v0.x * s0, v0.y * s0, v0.z * s0, v0.w * s0);
        *(float4*)&Bs[lr + 8][lc] = make_float4(v1.x * s1, v1.y * s1, v1.z * s1, v1.w * s1);
        __syncthreads();
#pragma unroll
        for (int kk = 0; kk < 16; kk++) {
            float4 a0 = *(float4*)&As[kk][ty * 8], a1 = *(float4*)&As[kk][ty * 8 + 4];
            float4 b0 = *(float4*)&Bs[kk][tx * 8], b1 = *(float4*)&Bs[kk][tx * 8 + 4];
            float avv[8] = {a0.x, a0.y, a0.z, a0.w, a1.x, a1.y, a1.z, a1.w};
            float bvv[8] = {b0.x, b0.y, b0.z, b0.w, b1.x, b1.y, b1.z, b1.w};
#pragma unroll
            for (int i = 0; i < 8; i++)
#pragma unroll
                for (int j = 0; j < 8; j++) acc[i][j] += avv[i] * bvv[j];
        }
        __syncthreads();
    }
#pragma unroll
    for (int c = 0; c < 8; c++) {
        float* orow = &g_oa[((size_t)b * Cn + c0 + tx * 8 + c) * Tn + j0 + ty * 8];
        *(float4*)&orow[0] = make_float4(acc[0][c], acc[1][c], acc[2][c], acc[3][c]);
        *(float4*)&orow[4] = make_float4(acc[4][c], acc[5][c], acc[6][c], acc[7][c]);
    }
}

// ------------- causal conv (KS=3, pad-left 2) + relu; WHICH=2 fuses final --
template <int WHICH>
__global__ __launch_bounds__(256) void conv_kernel(const float* __restrict__ bias,
                                                   const float* __restrict__ x,
                                                   float* __restrict__ out_final) {
    const float* in = (WHICH == 1) ? g_oa : g_h1;
    const float* w  = (WHICH == 1) ? g_w1 : g_w2;
    float* out = (WHICH == 1) ? g_h1 : out_final;
    int b = blockIdx.z;
    int t0 = blockIdx.x * 128, o0 = blockIdx.y * 128;
    int tid = threadIdx.x;
    int tx = tid & 15, ty = tid >> 4;
    __shared__ float Ws[128][28];   // [o][cc*3+k], 24 used
    __shared__ float In_s[8][136];  // [cc][t0-2 .. t0+127], 130 used
    float acc[8][8] = {};
    int wr = tid >> 1, wo = (tid & 1) * 12;
    for (int c0 = 0; c0 < Cn; c0 += 8) {
#pragma unroll
        for (int q = 0; q < 3; q++)
            *(float4*)&Ws[wr][wo + q * 4] =
                *(const float4*)&w[(o0 + wr) * (Cn * 3) + c0 * 3 + wo + q * 4];
        for (int idx = tid; idx < 8 * 130; idx += 256) {
            int cc = idx / 130, tt = idx - cc * 130;
            int gt = t0 - 2 + tt;
            In_s[cc][tt] = (gt >= 0)
                ? in[((size_t)b * Cn + c0 + cc) * Tn + gt] : 0.f;
        }
        __syncthreads();
#pragma unroll
        for (int cc = 0; cc < 8; cc++) {
            float4 wa = *(float4*)&In_s[cc][tx * 8];
            float4 wb = *(float4*)&In_s[cc][tx * 8 + 4];
            float4 wc = *(float4*)&In_s[cc][tx * 8 + 8];
            float win[12] = {wa.x, wa.y, wa.z, wa.w, wb.x, wb.y, wb.z, wb.w,
                             wc.x, wc.y, wc.z, wc.w};
#pragma unroll
            for (int i = 0; i < 8; i++) {
                float w0 = Ws[ty * 8 + i][cc * 3 + 0];
                float w1 = Ws[ty * 8 + i][cc * 3 + 1];
                float w2 = Ws[ty * 8 + i][cc * 3 + 2];
#pragma unroll
                for (int j = 0; j < 8; j++)
                    acc[i][j] += w0 * win[j] + w1 * win[j + 1] + w2 * win[j + 2];
            }
        }
        __syncthreads();
    }
    float wxv[8];
    if (WHICH == 2) {
#pragma unroll
        for (int j = 0; j < 8; j++) wxv[j] = g_wx[b * Tn + t0 + tx * 8 + j];
    }
#pragma unroll
    for (int i = 0; i < 8; i++) {
        int o = o0 + ty * 8 + i;
        float bo = bias[o];
        float vals[8];
        if (WHICH == 2) {
            const float* xrow = &x[((size_t)b * Cn + o) * Tn + t0 + tx * 8];
            float4 x0 = *(const float4*)&xrow[0];
            float4 x1 = *(const float4*)&xrow[4];
            float xv[8] = {x0.x, x0.y, x0.z, x0.w, x1.x, x1.y, x1.z, x1.w};
#pragma unroll
            for (int j = 0; j < 8; j++) {
                float h = fmaxf(acc[i][j] + bo, 0.f);
                vals[j] = fmaxf(h + xv[j] + wxv[j] * xv[j], 0.f);
            }
        } else {
#pragma unroll
            for (int j = 0; j < 8; j++) vals[j] = fmaxf(acc[i][j] + bo, 0.f);
        }
        float* orow = &out[((size_t)b * Cn + o) * Tn + t0 + tx * 8];
        *(float4*)&orow[0] = make_float4(vals[0], vals[1], vals[2], vals[3]);
        *(float4*)&orow[4] = make_float4(vals[4], vals[5], vals[6], vals[7]);
    }
}

// ---------------------------------------------------------------------------
extern "C" void kernel_launch(void* const* d_in, const int* in_sizes, int n_in,
                              void* d_out, int out_size) {
    const float* x   = (const float*)d_in[0];
    const float* Wq  = (const float*)d_in[1];
    const float* bq  = (const float*)d_in[2];
    const float* Wk  = (const float*)d_in[3];
    const float* bk  = (const float*)d_in[4];
    const float* Wv  = (const float*)d_in[5];
    const float* bv  = (const float*)d_in[6];
    const float* c1v = (const float*)d_in[7];
    const float* c1g = (const float*)d_in[8];
    const float* c1b = (const float*)d_in[9];
    const float* c2v = (const float*)d_in[10];
    const float* c2g = (const float*)d_in[11];
    const float* c2b = (const float*)d_in[12];
    float* out = (float*)d_out;

    wnorm_kernel<<<Cn, 256>>>(c1v, c1g, 0);
    wnorm_kernel<<<Cn, 256>>>(c2v, c2g, 1);

    dim3 gQ(Tn / 128, 256 / 128, Bn);
    gemm_qkv<<<gQ, 256>>>(x, Wq, bq, 0);
    gemm_qkv<<<gQ, 256>>>(x, Wk, bk, 1);
    gemm_qkv<<<gQ, 256>>>(x, Wv, bv, 2);

    gemm_scores<<<dim3(Tn / 128, Tn / 128, Bn), 256>>>();
    invcol_kernel<<<(Bn * Tn) / 256, 256>>>();
    row_sum<<<dim3(Tn / 8, Bn), 256>>>();
    wx_softmax<<<Bn, 256>>>();
    gemm_av<<<dim3(Tn / 128, Cn / 128, Bn), 256>>>();

    conv_kernel<1><<<dim3(Tn / 128, Cn / 128, Bn), 256>>>(c1b, x, nullptr);
    conv_kernel<2><<<dim3(Tn / 128, Cn / 128, Bn), 256>>>(c2b, x, out);
}

// round 3
// speedup vs baseline: 1.1404x; 1.1404x over previous
#include <cuda_runtime.h>
#include <cstdint>

#define Bn   16
#define Cn   256
#define Tn   1024
#define KEYn 256
#define INV_SQRT_K 0.0625f

// ---------------- scratch (device globals; no allocation allowed) ----------
__device__ float g_q[Bn * KEYn * Tn];            // channel-major [B,KEY,T]
__device__ float g_k[Bn * KEYn * Tn];            // channel-major [B,KEY,T]
__device__ float g_v[Bn * Tn * Cn];              // token-major   [B,T,C]
__device__ float g_attn[(size_t)Bn * Tn * Tn];   // exp(scores), unnormalized
__device__ float g_colpart[(size_t)16 * Bn * Tn];
__device__ float g_invcol[Bn * Tn];
__device__ float g_rowsum[Bn * Tn];
__device__ float g_wx[Bn * Tn];
__device__ float g_oa[Bn * Cn * Tn];
__device__ float g_h1[Bn * Cn * Tn];
__device__ float g_w1[Cn * Cn * 3];
__device__ float g_w2[Cn * Cn * 3];

// ---------------- weight norm ----------------------------------------------
__global__ __launch_bounds__(256) void wnorm_kernel(const float* __restrict__ v,
                                                    const float* __restrict__ g,
                                                    int which) {
    float* w = which ? g_w2 : g_w1;
    int o = blockIdx.x;
    int tid = threadIdx.x;
    __shared__ float red[256];
    float s = 0.f;
    for (int i = tid; i < Cn * 3; i += 256) {
        float t = v[o * Cn * 3 + i];
        s += t * t;
    }
    red[tid] = s;
    __syncthreads();
    for (int st = 128; st > 0; st >>= 1) {
        if (tid < st) red[tid] += red[tid + st];
        __syncthreads();
    }
    float scale = g[o] * rsqrtf(red[0]);
    for (int i = tid; i < Cn * 3; i += 256)
        w[o * Cn * 3 + i] = v[o * Cn * 3 + i] * scale;
}

// ------- q/k projection, channel-major out: out[b,n,t] = sum_c W[c,n]x[b,c,t]
__global__ __launch_bounds__(256) void gemm_qk_t(const float* __restrict__ x,
                                                 const float* __restrict__ W,
                                                 const float* __restrict__ bias,
                                                 int which) {
    float* out = which ? g_k : g_q;
    __shared__ float As[16][64];   // [c][n] from W
    __shared__ float Bs[16][64];   // [c][t] from x
    int b = blockIdx.z;
    int t0 = blockIdx.x * 64, n0 = blockIdx.y * 64;
    int tid = threadIdx.x;
    int tx = tid & 15, ty = tid >> 4;
    int lk = tid >> 4, lm = (tid & 15) * 4;
    const float* xb = x + (size_t)b * Cn * Tn;
    float acc[4][4] = {};
    for (int c0 = 0; c0 < Cn; c0 += 16) {
        *(float4*)&As[lk][lm] = *(const float4*)&W[(c0 + lk) * KEYn + n0 + lm];
        *(float4*)&Bs[lk][lm] = *(const float4*)&xb[(c0 + lk) * Tn + t0 + lm];
        __syncthreads();
#pragma unroll
        for (int kk = 0; kk < 16; kk++) {
            float4 a4 = *(float4*)&As[kk][ty * 4];
            float4 b4 = *(float4*)&Bs[kk][tx * 4];
            float av[4] = {a4.x, a4.y, a4.z, a4.w};
            float bv[4] = {b4.x, b4.y, b4.z, b4.w};
#pragma unroll
            for (int i = 0; i < 4; i++)
#pragma unroll
                for (int j = 0; j < 4; j++) acc[i][j] += av[i] * bv[j];
        }
        __syncthreads();
    }
#pragma unroll
    for (int i = 0; i < 4; i++) {
        int n = n0 + ty * 4 + i;
        float bo = bias[n];
        *(float4*)&out[((size_t)b * KEYn + n) * Tn + t0 + tx * 4] =
            make_float4(acc[i][0] + bo, acc[i][1] + bo, acc[i][2] + bo, acc[i][3] + bo);
    }
}

// ------- v projection, token-major out: v[b,t,c] = sum_cin x[b,cin,t]W[cin,c]
__global__ __launch_bounds__(256) void gemm_v(const float* __restrict__ x,
                                              const float* __restrict__ W,
                                              const float* __restrict__ bias) {
    __shared__ float As[16][64];   // [cin][t]
    __shared__ float Bs[16][64];   // [cin][c]
    int b = blockIdx.z;
    int t0 = blockIdx.x * 64, n0 = blockIdx.y * 64;
    int tid = threadIdx.x;
    int tx = tid & 15, ty = tid >> 4;
    int lk = tid >> 4, lm = (tid & 15) * 4;
    const float* xb = x + (size_t)b * Cn * Tn;
    float acc[4][4] = {};
    for (int c0 = 0; c0 < Cn; c0 += 16) {
        *(float4*)&As[lk][lm] = *(const float4*)&xb[(c0 + lk) * Tn + t0 + lm];
        *(float4*)&Bs[lk][lm] = *(const float4*)&W[(c0 + lk) * Cn + n0 + lm];
        __syncthreads();
#pragma unroll
        for (int kk = 0; kk < 16; kk++) {
            float4 a4 = *(float4*)&As[kk][ty * 4];
            float4 b4 = *(float4*)&Bs[kk][tx * 4];
            float av[4] = {a4.x, a4.y, a4.z, a4.w};
            float bv[4] = {b4.x, b4.y, b4.z, b4.w};
#pragma unroll
            for (int i = 0; i < 4; i++)
#pragma unroll
                for (int j = 0; j < 4; j++) acc[i][j] += av[i] * bv[j];
        }
        __syncthreads();
    }
    float4 bb = *(const float4*)&bias[n0 + tx * 4];
    float bvv[4] = {bb.x, bb.y, bb.z, bb.w};
#pragma unroll
    for (int i = 0; i < 4; i++) {
        int t = t0 + ty * 4 + i;
        *(float4*)&g_v[((size_t)b * Tn + t) * Cn + n0 + tx * 4] =
            make_float4(acc[i][0] + bvv[0], acc[i][1] + bvv[1],
                        acc[i][2] + bvv[2], acc[i][3] + bvv[3]);
    }
}

// ------- scores: e[b,j,i] = (i<=j) ? exp(q_j·k_i/16) : 0 + column partials --
__global__ __launch_bounds__(256) void gemm_scores() {
    int b = blockIdx.z;
    int i0 = blockIdx.x * 64, j0 = blockIdx.y * 64;
    int tid = threadIdx.x;
    int tx = tid & 15, ty = tid >> 4;
    float* S = g_attn + (size_t)b * Tn * Tn;
    float* cpart = g_colpart + (size_t)(j0 >> 6) * Bn * Tn + b * Tn + i0;
    if (i0 > j0) {  // fully masked
        float4 z = make_float4(0.f, 0.f, 0.f, 0.f);
#pragma unroll
        for (int i = 0; i < 4; i++) {
            int j = j0 + ty * 4 + i;
            *(float4*)&S[(size_t)j * Tn + i0 + tx * 4] = z;
        }
        if (tid < 64) cpart[tid] = 0.f;
        return;
    }
    __shared__ float Qs[16][64];   // [key][j] direct from qT
    __shared__ float Ks[16][64];   // [key][i] direct from kT
    __shared__ float cred[16][64];
    int lk = tid >> 4, lm = (tid & 15) * 4;
    const float* qb = g_q + (size_t)b * KEYn * Tn;
    const float* kb = g_k + (size_t)b * KEYn * Tn;
    float acc[4][4] = {};
    for (int kc = 0; kc < KEYn; kc += 16) {
        *(float4*)&Qs[lk][lm] = *(const float4*)&qb[(size_t)(kc + lk) * Tn + j0 + lm];
        *(float4*)&Ks[lk][lm] = *(const float4*)&kb[(size_t)(kc + lk) * Tn + i0 + lm];
        __syncthreads();
#pragma unroll
        for (int kk = 0; kk < 16; kk++) {
            float4 a4 = *(float4*)&Qs[kk][ty * 4];
            float4 b4 = *(float4*)&Ks[kk][tx * 4];
            float av[4] = {a4.x, a4.y, a4.z, a4.w};
            float bv[4] = {b4.x, b4.y, b4.z, b4.w};
#pragma unroll
            for (int i = 0; i < 4; i++)
#pragma unroll
                for (int j = 0; j < 4; j++) acc[i][j] += av[i] * bv[j];
        }
        __syncthreads();
    }
    float csum[4] = {};
#pragma unroll
    for (int r = 0; r < 4; r++) {
        int j = j0 + ty * 4 + r;
        float e[4];
#pragma unroll
        for (int c = 0; c < 4; c++) {
            int i = i0 + tx * 4 + c;
            e[c] = (i <= j) ? __expf(acc[r][c] * INV_SQRT_K) : 0.f;
            csum[c] += e[c];
        }
        *(float4*)&S[(size_t)j * Tn + i0 + tx * 4] =
            make_float4(e[0], e[1], e[2], e[3]);
    }
#pragma unroll
    for (int c = 0; c < 4; c++) cred[ty][tx * 4 + c] = csum[c];
    __syncthreads();
    if (tid < 64) {
        float s = 0.f;
#pragma unroll
        for (int k = 0; k < 16; k++) s += cred[k][tid];
        cpart[tid] = s;
    }
}

// ------- invcol[b,i] = 1 / sum_p colpart[p][b,i] ---------------------------
__global__ __launch_bounds__(256) void invcol_kernel() {
    int idx = blockIdx.x * 256 + threadIdx.x;
    float s = 0.f;
#pragma unroll
    for (int p = 0; p < 16; p++) s += g_colpart[(size_t)p * Bn * Tn + idx];
    g_invcol[idx] = 1.f / s;
}

// ------- rowsum[b,j] = sum_i e[b,j,i] * invcol[b,i] ------------------------
__global__ __launch_bounds__(256) void row_sum() {
    int b = blockIdx.y;
    int j = blockIdx.x * 8 + (threadIdx.x >> 5);
    int lane = threadIdx.x & 31;
    const float* row = g_attn + (size_t)b * Tn * Tn + (size_t)j * Tn;
    const float* inv = g_invcol + b * Tn;
    float s = 0.f;
    for (int i = lane; i < Tn; i += 32) s += row[i] * inv[i];
#pragma unroll
    for (int o = 16; o > 0; o >>= 1) s += __shfl_xor_sync(0xffffffffu, s, o);
    if (lane == 0) g_rowsum[b * Tn + j] = s;
}

// ------- weight_x[b,:] = softmax_j(rowsum[b,:]) ----------------------------
__global__ __launch_bounds__(256) void wx_softmax() {
    int b = blockIdx.x;
    int tid = threadIdx.x;
    __shared__ float red[256];
    const float* r = g_rowsum + b * Tn;
    float m = -1e30f;
    for (int j = tid; j < Tn; j += 256) m = fmaxf(m, r[j]);
    red[tid] = m;
    __syncthreads();
    for (int st = 128; st > 0; st >>= 1) {
        if (tid < st) red[tid] = fmaxf(red[tid], red[tid + st]);
        __syncthreads();
    }
    m = red[0];
    __syncthreads();
    float sum = 0.f;
    for (int j = tid; j < Tn; j += 256) sum += __expf(r[j] - m);
    red[tid] = sum;
    __syncthreads();
    for (int st = 128; st > 0; st >>= 1) {
        if (tid < st) red[tid] += red[tid + st];
        __syncthreads();
    }
    float inv = 1.f / red[0];
    for (int j = tid; j < Tn; j += 256)
        g_wx[b * Tn + j] = __expf(r[j] - m) * inv;
}

// ------- out_attn[b,c,j] = sum_i e[b,j,i]*invcol[i]*v[b,i,c] ---------------
__global__ __launch_bounds__(256) void gemm_av() {
    int b = blockIdx.z;
    int j0 = blockIdx.x * 64, c0 = blockIdx.y * 64;
    int tid = threadIdx.x;
    int tx = tid & 15, ty = tid >> 4;
    __shared__ float As[16][68];   // [i_k][j] transposed exp-weights
    __shared__ float Bs[16][64];   // [i_k][c] scaled V rows
    const float* A = g_attn + (size_t)b * Tn * Tn;
    const float* V = g_v + (size_t)b * Tn * Cn;
    const float* inv = g_invcol + b * Tn;
    int lj = tid >> 2, ls = (tid & 3) * 4;
    int lk = tid >> 4, lm = (tid & 15) * 4;
    float acc[4][4] = {};
    int kend = j0 + 64;   // causal: e[j,i]==0 for i>j
    for (int ii = 0; ii < kend; ii += 16) {
        float4 av = *(const float4*)&A[(size_t)(j0 + lj) * Tn + ii + ls];
        As[ls + 0][lj] = av.x; As[ls + 1][lj] = av.y;
        As[ls + 2][lj] = av.z; As[ls + 3][lj] = av.w;
        float sc = inv[ii + lk];
        float4 v4 = *(const float4*)&V[(size_t)(ii + lk) * Cn + c0 + lm];
        *(float4*)&Bs[lk][lm] = make_float4(v4.x * sc, v4.y * sc, v4.z * sc, v4.w * sc);
        __syncthreads();
#pragma unroll
        for (int kk = 0; kk < 16; kk++) {
            float4 a4 = *(float4*)&As[kk][ty * 4];
            float4 b4 = *(float4*)&Bs[kk][tx * 4];
            float avv[4] = {a4.x, a4.y, a4.z, a4.w};
            float bvv[4] = {b4.x, b4.y, b4.z, b4.w};
#pragma unroll
            for (int i = 0; i < 4; i++)
#pragma unroll
                for (int j = 0; j < 4; j++) acc[i][j] += avv[i] * bvv[j];
        }
        __syncthreads();
    }
#pragma unroll
    for (int i = 0; i < 4; i++)
#pragma unroll
        for (int jn = 0; jn < 4; jn++)
            g_oa[((size_t)b * Cn + c0 + tx * 4 + jn) * Tn + j0 + ty * 4 + i] = acc[i][jn];
}

// ------- causal conv (KS=3, pad-left 2) + relu; WHICH=2 fuses residual -----
template <int WHICH>
__global__ __launch_bounds__(256) void conv_kernel(const float* __restrict__ bias,
                                                   const float* __restrict__ x,
                                                   float* __restrict__ out_final) {
    const float* in = (WHICH == 1) ? g_oa : g_h1;
    const float* w  = (WHICH == 1) ? g_w1 : g_w2;
    float* out = (WHICH == 1) ? g_h1 : out_final;
    int b = blockIdx.z;
    int t0 = blockIdx.x * 64, o0 = blockIdx.y * 64;
    int tid = threadIdx.x;
    int tx = tid & 15, ty = tid >> 4;
    __shared__ float Ws[64][48];
    __shared__ float In_s[16][72];
    float acc[4][4] = {};
    int wrow = tid >> 2;
    for (int c0 = 0; c0 < Cn; c0 += 16) {
#pragma unroll
        for (int r = 0; r < 3; r++) {
            int off = ((tid & 3) + 4 * r) * 4;
            *(float4*)&Ws[wrow][off] =
                *(const float4*)&w[(o0 + wrow) * (Cn * 3) + c0 * 3 + off];
        }
        for (int idx = tid; idx < 16 * 66; idx += 256) {
            int cc = idx / 66, tt = idx % 66;
            int gt = t0 - 2 + tt;
            In_s[cc][tt] = (gt >= 0)
                ? in[((size_t)b * Cn + c0 + cc) * Tn + gt] : 0.f;
        }
        __syncthreads();
#pragma unroll
        for (int cc = 0; cc < 16; cc++) {
            float win[6];
#pragma unroll
            for (int u = 0; u < 6; u++) win[u] = In_s[cc][tx * 4 + u];
#pragma unroll
            for (int i = 0; i < 4; i++) {
                float w0 = Ws[ty * 4 + i][cc * 3 + 0];
                float w1 = Ws[ty * 4 + i][cc * 3 + 1];
                float w2 = Ws[ty * 4 + i][cc * 3 + 2];
#pragma unroll
                for (int j = 0; j < 4; j++)
                    acc[i][j] += w0 * win[j] + w1 * win[j + 1] + w2 * win[j + 2];
            }
        }
        __syncthreads();
    }
    float wxv[4];
    if (WHICH == 2) {
#pragma unroll
        for (int j = 0; j < 4; j++) wxv[j] = g_wx[b * Tn + t0 + tx * 4 + j];
    }
#pragma unroll
    for (int i = 0; i < 4; i++) {
        int o = o0 + ty * 4 + i;
        float bo = bias[o];
        float vals[4];
#pragma unroll
        for (int j = 0; j < 4; j++) {
            float h = fmaxf(acc[i][j] + bo, 0.f);
            if (WHICH == 2) {
                int t = t0 + tx * 4 + j;
                float xv = x[((size_t)b * Cn + o) * Tn + t];
                h = fmaxf(h + xv + wxv[j] * xv, 0.f);
            }
            vals[j] = h;
        }
        *(float4*)&out[((size_t)b * Cn + o) * Tn + t0 + tx * 4] =
            make_float4(vals[0], vals[1], vals[2], vals[3]);
    }
}

// ---------------------------------------------------------------------------
extern "C" void kernel_launch(void* const* d_in, const int* in_sizes, int n_in,
                              void* d_out, int out_size) {
    const float* x   = (const float*)d_in[0];
    const float* Wq  = (const float*)d_in[1];
    const float* bq  = (const float*)d_in[2];
    const float* Wk  = (const float*)d_in[3];
    const float* bk  = (const float*)d_in[4];
    const float* Wv  = (const float*)d_in[5];
    const float* bv  = (const float*)d_in[6];
    const float* c1v = (const float*)d_in[7];
    const float* c1g = (const float*)d_in[8];
    const float* c1b = (const float*)d_in[9];
    const float* c2v = (const float*)d_in[10];
    const float* c2g = (const float*)d_in[11];
    const float* c2b = (const float*)d_in[12];
    float* out = (float*)d_out;

    wnorm_kernel<<<Cn, 256>>>(c1v, c1g, 0);
    wnorm_kernel<<<Cn, 256>>>(c2v, c2g, 1);

    dim3 gQ(Tn / 64, KEYn / 64, Bn);
    gemm_qk_t<<<gQ, 256>>>(x, Wq, bq, 0);
    gemm_qk_t<<<gQ, 256>>>(x, Wk, bk, 1);
    gemm_v<<<dim3(Tn / 64, Cn / 64, Bn), 256>>>(x, Wv, bv);

    gemm_scores<<<dim3(Tn / 64, Tn / 64, Bn), 256>>>();
    invcol_kernel<<<(Bn * Tn) / 256, 256>>>();
    row_sum<<<dim3(Tn / 8, Bn), 256>>>();
    wx_softmax<<<Bn, 256>>>();
    gemm_av<<<dim3(Tn / 64, Cn / 64, Bn), 256>>>();

    conv_kernel<1><<<dim3(Tn / 64, Cn / 64, Bn), 256>>>(c1b, x, nullptr);
    conv_kernel<2><<<dim3(Tn / 64, Cn / 64, Bn), 256>>>(c2b, x, out);
}

// round 5
// speedup vs baseline: 1.5747x; 1.3809x over previous
#include <cuda_runtime.h>
#include <mma.h>
#include <cstdint>

using namespace nvcuda;

#define Bn   16
#define Cn   256
#define Tn   1024
#define KEYn 256
#define INV_SQRT_K 0.0625f

// ---------------- scratch (device globals; no allocation allowed) ----------
__device__ float g_q[Bn * KEYn * Tn];            // channel-major [B,KEY,T]
__device__ float g_k[Bn * KEYn * Tn];            // channel-major [B,KEY,T]
__device__ float g_v[Bn * Tn * Cn];              // token-major   [B,T,C]
__device__ float g_attn[(size_t)Bn * Tn * Tn];   // exp(scores), unnormalized
__device__ float g_colpart[(size_t)16 * Bn * Tn];
__device__ float g_invcol[Bn * Tn];
__device__ float g_rowsum[Bn * Tn];
__device__ float g_wx[Bn * Tn];
__device__ float g_oa[Bn * Cn * Tn];
__device__ float g_h1[Bn * Cn * Tn];
__device__ float g_ws1[3 * Cn * Cn];             // weight-normed, split [r][c][o]
__device__ float g_ws2[3 * Cn * Cn];

// ---------------- weight norm -> split per-tap transposed layout -----------
__global__ __launch_bounds__(256) void wnorm_kernel(const float* __restrict__ v,
                                                    const float* __restrict__ g,
                                                    int which) {
    float* w = which ? g_ws2 : g_ws1;
    int o = blockIdx.x;
    int tid = threadIdx.x;
    __shared__ float red[256];
    float s = 0.f;
    for (int i = tid; i < Cn * 3; i += 256) {
        float t = v[o * Cn * 3 + i];
        s += t * t;
    }
    red[tid] = s;
    __syncthreads();
    for (int st = 128; st > 0; st >>= 1) {
        if (tid < st) red[tid] += red[tid + st];
        __syncthreads();
    }
    float scale = g[o] * rsqrtf(red[0]);
    for (int i = tid; i < Cn * 3; i += 256) {
        int c = i / 3, r = i - c * 3;
        w[(r * Cn + c) * Cn + o] = v[o * Cn * 3 + i] * scale;
    }
}

// ------- q/k projection (FFMA path), channel-major out ---------------------
__global__ __launch_bounds__(256) void gemm_qk_t(const float* __restrict__ x,
                                                 const float* __restrict__ W,
                                                 const float* __restrict__ bias,
                                                 int which) {
    float* out = which ? g_k : g_q;
    __shared__ float As[16][64];
    __shared__ float Bs[16][64];
    int b = blockIdx.z;
    int t0 = blockIdx.x * 64, n0 = blockIdx.y * 64;
    int tid = threadIdx.x;
    int tx = tid & 15, ty = tid >> 4;
    int lk = tid >> 4, lm = (tid & 15) * 4;
    const float* xb = x + (size_t)b * Cn * Tn;
    float acc[4][4] = {};
    for (int c0 = 0; c0 < Cn; c0 += 16) {
        *(float4*)&As[lk][lm] = *(const float4*)&W[(c0 + lk) * KEYn + n0 + lm];
        *(float4*)&Bs[lk][lm] = *(const float4*)&xb[(c0 + lk) * Tn + t0 + lm];
        __syncthreads();
#pragma unroll
        for (int kk = 0; kk < 16; kk++) {
            float4 a4 = *(float4*)&As[kk][ty * 4];
            float4 b4 = *(float4*)&Bs[kk][tx * 4];
            float av[4] = {a4.x, a4.y, a4.z, a4.w};
            float bv[4] = {b4.x, b4.y, b4.z, b4.w};
#pragma unroll
            for (int i = 0; i < 4; i++)
#pragma unroll
                for (int j = 0; j < 4; j++) acc[i][j] += av[i] * bv[j];
        }
        __syncthreads();
    }
#pragma unroll
    for (int i = 0; i < 4; i++) {
        int n = n0 + ty * 4 + i;
        float bo = bias[n];
        *(float4*)&out[((size_t)b * KEYn + n) * Tn + t0 + tx * 4] =
            make_float4(acc[i][0] + bo, acc[i][1] + bo, acc[i][2] + bo, acc[i][3] + bo);
    }
}

// ------- v projection (FFMA path), token-major out -------------------------
__global__ __launch_bounds__(256) void gemm_v(const float* __restrict__ x,
                                              const float* __restrict__ W,
                                              const float* __restrict__ bias) {
    __shared__ float As[16][64];
    __shared__ float Bs[16][64];
    int b = blockIdx.z;
    int t0 = blockIdx.x * 64, n0 = blockIdx.y * 64;
    int tid = threadIdx.x;
    int tx = tid & 15, ty = tid >> 4;
    int lk = tid >> 4, lm = (tid & 15) * 4;
    const float* xb = x + (size_t)b * Cn * Tn;
    float acc[4][4] = {};
    for (int c0 = 0; c0 < Cn; c0 += 16) {
        *(float4*)&As[lk][lm] = *(const float4*)&xb[(c0 + lk) * Tn + t0 + lm];
        *(float4*)&Bs[lk][lm] = *(const float4*)&W[(c0 + lk) * Cn + n0 + lm];
        __syncthreads();
#pragma unroll
        for (int kk = 0; kk < 16; kk++) {
            float4 a4 = *(float4*)&As[kk][ty * 4];
            float4 b4 = *(float4*)&Bs[kk][tx * 4];
            float av[4] = {a4.x, a4.y, a4.z, a4.w};
            float bv[4] = {b4.x, b4.y, b4.z, b4.w};
#pragma unroll
            for (int i = 0; i < 4; i++)
#pragma unroll
                for (int j = 0; j < 4; j++) acc[i][j] += av[i] * bv[j];
        }
        __syncthreads();
    }
    float4 bb = *(const float4*)&bias[n0 + tx * 4];
    float bvv[4] = {bb.x, bb.y, bb.z, bb.w};
#pragma unroll
    for (int i = 0; i < 4; i++) {
        int t = t0 + ty * 4 + i;
        *(float4*)&g_v[((size_t)b * Tn + t) * Cn + n0 + tx * 4] =
            make_float4(acc[i][0] + bvv[0], acc[i][1] + bvv[1],
                        acc[i][2] + bvv[2], acc[i][3] + bvv[3]);
    }
}

// helper: convert fragment floats to tf32
template <typename FragT>
__device__ __forceinline__ void to_tf32(FragT& f) {
#pragma unroll
    for (int i = 0; i < f.num_elements; i++) f.x[i] = wmma::__float_to_tf32(f.x[i]);
}

// ------- scores (tf32 wmma): e[b,j,i] = (i<=j)?exp(q_j·k_i/16):0 + colparts -
__global__ __launch_bounds__(256) void gemm_scores() {
    int b = blockIdx.z;
    int i0 = blockIdx.x * 64, j0 = blockIdx.y * 64;
    int tid = threadIdx.x;
    float* S = g_attn + (size_t)b * Tn * Tn;
    float* cpart = g_colpart + (size_t)(j0 >> 6) * Bn * Tn + b * Tn + i0;
    int c = tid & 63, rb = tid >> 6;
    if (i0 > j0) {  // fully masked
#pragma unroll
        for (int rr = 0; rr < 16; rr++)
            S[(size_t)(j0 + rb * 16 + rr) * Tn + i0 + c] = 0.f;
        if (tid < 64) cpart[tid] = 0.f;
        return;
    }
    __shared__ float Qs[16][72];   // [key][j]
    __shared__ float Ks[16][72];   // [key][i]
    __shared__ float Ss[64][72];
    __shared__ float cred[4][64];
    int wid = tid >> 5;
    int m_off = (wid & 3) * 16;
    int n_base = (wid >> 2) * 32;
    const float* qb = g_q + (size_t)b * KEYn * Tn;
    const float* kb = g_k + (size_t)b * KEYn * Tn;
    wmma::fragment<wmma::accumulator, 16, 16, 8, float> acc[2];
    wmma::fill_fragment(acc[0], 0.f);
    wmma::fill_fragment(acc[1], 0.f);
    int lr = tid >> 4, lc = (tid & 15) * 4;
    for (int kc = 0; kc < KEYn; kc += 16) {
        *(float4*)&Qs[lr][lc] = *(const float4*)&qb[(size_t)(kc + lr) * Tn + j0 + lc];
        *(float4*)&Ks[lr][lc] = *(const float4*)&kb[(size_t)(kc + lr) * Tn + i0 + lc];
        __syncthreads();
#pragma unroll
        for (int ks = 0; ks < 16; ks += 8) {
            wmma::fragment<wmma::matrix_a, 16, 16, 8, wmma::precision::tf32, wmma::col_major> a;
            wmma::load_matrix_sync(a, &Qs[ks][m_off], 72);
            to_tf32(a);
#pragma unroll
            for (int nf = 0; nf < 2; nf++) {
                wmma::fragment<wmma::matrix_b, 16, 16, 8, wmma::precision::tf32, wmma::row_major> bf;
                wmma::load_matrix_sync(bf, &Ks[ks][n_base + nf * 16], 72);
                to_tf32(bf);
                wmma::mma_sync(acc[nf], a, bf, acc[nf]);
            }
        }
        __syncthreads();
    }
    wmma::store_matrix_sync(&Ss[m_off][n_base], acc[0], 72, wmma::mem_row_major);
    wmma::store_matrix_sync(&Ss[m_off][n_base + 16], acc[1], 72, wmma::mem_row_major);
    __syncthreads();
    float csum = 0.f;
#pragma unroll
    for (int rr = 0; rr < 16; rr++) {
        int row = rb * 16 + rr;
        int j = j0 + row, i = i0 + c;
        float e = (i <= j) ? __expf(Ss[row][c] * INV_SQRT_K) : 0.f;
        S[(size_t)j * Tn + i] = e;
        csum += e;
    }
    cred[rb][c] = csum;
    __syncthreads();
    if (tid < 64) {
        float s = cred[0][tid] + cred[1][tid] + cred[2][tid] + cred[3][tid];
        cpart[tid] = s;
    }
}

// ------- invcol[b,i] = 1 / sum_p colpart[p][b,i] ---------------------------
__global__ __launch_bounds__(256) void invcol_kernel() {
    int idx = blockIdx.x * 256 + threadIdx.x;
    float s = 0.f;
#pragma unroll
    for (int p = 0; p < 16; p++) s += g_colpart[(size_t)p * Bn * Tn + idx];
    g_invcol[idx] = 1.f / s;
}

// ------- rowsum[b,j] = sum_i e[b,j,i] * invcol[b,i] ------------------------
__global__ __launch_bounds__(256) void row_sum() {
    int b = blockIdx.y;
    int j = blockIdx.x * 8 + (threadIdx.x >> 5);
    int lane = threadIdx.x & 31;
    const float* row = g_attn + (size_t)b * Tn * Tn + (size_t)j * Tn;
    const float* inv = g_invcol + b * Tn;
    float s = 0.f;
    for (int i = lane; i < Tn; i += 32) s += row[i] * inv[i];
#pragma unroll
    for (int o = 16; o > 0; o >>= 1) s += __shfl_xor_sync(0xffffffffu, s, o);
    if (lane == 0) g_rowsum[b * Tn + j] = s;
}

// ------- weight_x[b,:] = softmax_j(rowsum[b,:]) ----------------------------
__global__ __launch_bounds__(256) void wx_softmax() {
    int b = blockIdx.x;
    int tid = threadIdx.x;
    __shared__ float red[256];
    const float* r = g_rowsum + b * Tn;
    float m = -1e30f;
    for (int j = tid; j < Tn; j += 256) m = fmaxf(m, r[j]);
    red[tid] = m;
    __syncthreads();
    for (int st = 128; st > 0; st >>= 1) {
        if (tid < st) red[tid] = fmaxf(red[tid], red[tid + st]);
        __syncthreads();
    }
    m = red[0];
    __syncthreads();
    float sum = 0.f;
    for (int j = tid; j < Tn; j += 256) sum += __expf(r[j] - m);
    red[tid] = sum;
    __syncthreads();
    for (int st = 128; st > 0; st >>= 1) {
        if (tid < st) red[tid] += red[tid + st];
        __syncthreads();
    }
    float inv = 1.f / red[0];
    for (int j = tid; j < Tn; j += 256)
        g_wx[b * Tn + j] = __expf(r[j] - m) * inv;
}

// ------- attn·V (tf32 wmma): oa[b,c,j] = sum_i e[j,i]*invcol[i]*v[i,c] -----
__global__ __launch_bounds__(256) void gemm_av() {
    int b = blockIdx.z;
    int j0 = blockIdx.x * 64, c0 = blockIdx.y * 64;
    int tid = threadIdx.x;
    __shared__ float As[16][72];   // [i][c] scaled v
    __shared__ float Es[64][24];   // [j][i-chunk]
    const float* A = g_attn + (size_t)b * Tn * Tn;
    const float* V = g_v + (size_t)b * Tn * Cn;
    const float* inv = g_invcol + b * Tn;
    int wid = tid >> 5;
    int m_off = (wid & 3) * 16;          // c
    int n_base = (wid >> 2) * 32;        // j
    wmma::fragment<wmma::accumulator, 16, 16, 8, float> acc[2];
    wmma::fill_fragment(acc[0], 0.f);
    wmma::fill_fragment(acc[1], 0.f);
    int ar = tid >> 4, ac = (tid & 15) * 4;
    int er = tid >> 2, ec = (tid & 3) * 4;
    int kend = j0 + 64;
    for (int ii = 0; ii < kend; ii += 16) {
        float sc = inv[ii + ar];
        float4 v4 = *(const float4*)&V[(size_t)(ii + ar) * Cn + c0 + ac];
        *(float4*)&As[ar][ac] = make_float4(v4.x * sc, v4.y * sc, v4.z * sc, v4.w * sc);
        *(float4*)&Es[er][ec] = *(const float4*)&A[(size_t)(j0 + er) * Tn + ii + ec];
        __syncthreads();
#pragma unroll
        for (int ks = 0; ks < 16; ks += 8) {
            wmma::fragment<wmma::matrix_a, 16, 16, 8, wmma::precision::tf32, wmma::col_major> a;
            wmma::load_matrix_sync(a, &As[ks][m_off], 72);
            to_tf32(a);
#pragma unroll
            for (int nf = 0; nf < 2; nf++) {
                wmma::fragment<wmma::matrix_b, 16, 16, 8, wmma::precision::tf32, wmma::col_major> bf;
                wmma::load_matrix_sync(bf, &Es[n_base + nf * 16][ks], 24);
                to_tf32(bf);
                wmma::mma_sync(acc[nf], a, bf, acc[nf]);
            }
        }
        __syncthreads();
    }
    float* obase = &g_oa[((size_t)b * Cn + c0 + m_off) * Tn + j0];
    wmma::store_matrix_sync(obase + n_base, acc[0], Tn, wmma::mem_row_major);
    wmma::store_matrix_sync(obase + n_base + 16, acc[1], Tn, wmma::mem_row_major);
}

// ------- causal conv (tf32 wmma implicit GEMM, KS=3) + fusion --------------
template <int WHICH>
__global__ __launch_bounds__(256) void conv_kernel(const float* __restrict__ bias,
                                                   const float* __restrict__ x,
                                                   float* __restrict__ out_final) {
    const float* in = (WHICH == 1) ? g_oa : g_h1;
    const float* w  = (WHICH == 1) ? g_ws1 : g_ws2;
    float* out = (WHICH == 1) ? g_h1 : out_final;
    int b = blockIdx.z;
    int t0 = blockIdx.x * 64, o0 = blockIdx.y * 64;
    int tid = threadIdx.x;
    __shared__ float As[3][16][72];   // [r][c][o]
    __shared__ float In3[3][16][72];  // [r][c][t-window per tap]
    __shared__ float Ss[64][72];
    int wid = tid >> 5;
    int m_off = (wid & 3) * 16;       // o
    int n_base = (wid >> 2) * 32;     // t
    wmma::fragment<wmma::accumulator, 16, 16, 8, float> acc[2];
    wmma::fill_fragment(acc[0], 0.f);
    wmma::fill_fragment(acc[1], 0.f);
    const float* inb = in + (size_t)b * Cn * Tn;
    for (int cc0 = 0; cc0 < Cn; cc0 += 16) {
        // weights: 3*16 rows of 64 floats (float4, aligned)
#pragma unroll
        for (int q = 0; q < 3; q++) {
            int lin = tid + q * 256;
            int row = lin >> 4, col = (lin & 15) * 4;
            int r = row >> 4, kk = row & 15;
            *(float4*)&As[r][kk][col] =
                *(const float4*)&w[((r * Cn) + cc0 + kk) * Cn + o0 + col];
        }
        // input windows via SCALAR loads (tap shift breaks float4 alignment):
        // In3[r][cc][n] = in[cc0+cc][t0+n-2+r]
#pragma unroll
        for (int q = 0; q < 12; q++) {
            int lin = tid + q * 256;          // 0..3071
            int r = lin >> 10;
            int rem = lin & 1023;
            int kk = rem >> 6, col = rem & 63;
            int gt = t0 + col - 2 + r;
            In3[r][kk][col] = (gt >= 0)
                ? inb[(size_t)(cc0 + kk) * Tn + gt] : 0.f;
        }
        __syncthreads();
#pragma unroll
        for (int r = 0; r < 3; r++) {
#pragma unroll
            for (int ks = 0; ks < 16; ks += 8) {
                wmma::fragment<wmma::matrix_a, 16, 16, 8, wmma::precision::tf32, wmma::col_major> a;
                wmma::load_matrix_sync(a, &As[r][ks][m_off], 72);
                to_tf32(a);
#pragma unroll
                for (int nf = 0; nf < 2; nf++) {
                    wmma::fragment<wmma::matrix_b, 16, 16, 8, wmma::precision::tf32, wmma::row_major> bf;
                    wmma::load_matrix_sync(bf, &In3[r][ks][n_base + nf * 16], 72);
                    to_tf32(bf);
                    wmma::mma_sync(acc[nf], a, bf, acc[nf]);
                }
            }
        }
        __syncthreads();
    }
    wmma::store_matrix_sync(&Ss[m_off][n_base], acc[0], 72, wmma::mem_row_major);
    wmma::store_matrix_sync(&Ss[m_off][n_base + 16], acc[1], 72, wmma::mem_row_major);
    __syncthreads();
    int row = tid >> 2, colb = (tid & 3) * 16;
    int o = o0 + row;
    float bo = bias[o];
    if (WHICH == 2) {
        const float* xrow = &x[((size_t)b * Cn + o) * Tn + t0 + colb];
        const float* wxp = &g_wx[b * Tn + t0 + colb];
        float* orow = &out[((size_t)b * Cn + o) * Tn + t0 + colb];
#pragma unroll
        for (int q = 0; q < 4; q++) {
            float4 xv = *(const float4*)&xrow[q * 4];
            float4 wx4 = *(const float4*)&wxp[q * 4];
            float4 res;
            float h0 = fmaxf(Ss[row][colb + q * 4 + 0] + bo, 0.f);
            float h1 = fmaxf(Ss[row][colb + q * 4 + 1] + bo, 0.f);
            float h2 = fmaxf(Ss[row][colb + q * 4 + 2] + bo, 0.f);
            float h3 = fmaxf(Ss[row][colb + q * 4 + 3] + bo, 0.f);
            res.x = fmaxf(h0 + xv.x + wx4.x * xv.x, 0.f);
            res.y = fmaxf(h1 + xv.y + wx4.y * xv.y, 0.f);
            res.z = fmaxf(h2 + xv.z + wx4.z * xv.z, 0.f);
            res.w = fmaxf(h3 + xv.w + wx4.w * xv.w, 0.f);
            *(float4*)&orow[q * 4] = res;
        }
    } else {
        float* orow = &out[((size_t)b * Cn + o) * Tn + t0 + colb];
#pragma unroll
        for (int q = 0; q < 4; q++) {
            float4 res;
            res.x = fmaxf(Ss[row][colb + q * 4 + 0] + bo, 0.f);
            res.y = fmaxf(Ss[row][colb + q * 4 + 1] + bo, 0.f);
            res.z = fmaxf(Ss[row][colb + q * 4 + 2] + bo, 0.f);
            res.w = fmaxf(Ss[row][colb + q * 4 + 3] + bo, 0.f);
            *(float4*)&orow[q * 4] = res;
        }
    }
}

// ---------------------------------------------------------------------------
extern "C" void kernel_launch(void* const* d_in, const int* in_sizes, int n_in,
                              void* d_out, int out_size) {
    const float* x   = (const float*)d_in[0];
    const float* Wq  = (const float*)d_in[1];
    const float* bq  = (const float*)d_in[2];
    const float* Wk  = (const float*)d_in[3];
    const float* bk  = (const float*)d_in[4];
    const float* Wv  = (const float*)d_in[5];
    const float* bv  = (const float*)d_in[6];
    const float* c1v = (const float*)d_in[7];
    const float* c1g = (const float*)d_in[8];
    const float* c1b = (const float*)d_in[9];
    const float* c2v = (const float*)d_in[10];
    const float* c2g = (const float*)d_in[11];
    const float* c2b = (const float*)d_in[12];
    float* out = (float*)d_out;

    wnorm_kernel<<<Cn, 256>>>(c1v, c1g, 0);
    wnorm_kernel<<<Cn, 256>>>(c2v, c2g, 1);

    dim3 gQ(Tn / 64, KEYn / 64, Bn);
    gemm_qk_t<<<gQ, 256>>>(x, Wq, bq, 0);
    gemm_qk_t<<<gQ, 256>>>(x, Wk, bk, 1);
    gemm_v<<<dim3(Tn / 64, Cn / 64, Bn), 256>>>(x, Wv, bv);

    gemm_scores<<<dim3(Tn / 64, Tn / 64, Bn), 256>>>();
    invcol_kernel<<<(Bn * Tn) / 256, 256>>>();
    row_sum<<<dim3(Tn / 8, Bn), 256>>>();
    wx_softmax<<<Bn, 256>>>();
    gemm_av<<<dim3(Tn / 64, Cn / 64, Bn), 256>>>();

    conv_kernel<1><<<dim3(Tn / 64, Cn / 64, Bn), 256>>>(c1b, x, nullptr);
    conv_kernel<2><<<dim3(Tn / 64, Cn / 64, Bn), 256>>>(c2b, x, out);
}

// round 6
// speedup vs baseline: 1.6730x; 1.0624x over previous
#include <cuda_runtime.h>
#include <mma.h>
#include <cstdint>

using namespace nvcuda;

#define Bn   16
#define Cn   256
#define Tn   1024
#define KEYn 256
#define INV_SQRT_K 0.0625f

// ---------------- scratch (device globals; no allocation allowed) ----------
__device__ float g_q[Bn * KEYn * Tn];            // channel-major [B,KEY,T]
__device__ float g_k[Bn * KEYn * Tn];            // channel-major [B,KEY,T]
__device__ float g_v[Bn * Tn * Cn];              // token-major   [B,T,C]
__device__ float g_attn[(size_t)Bn * Tn * Tn];   // exp(scores), unnormalized
__device__ float g_colpart[(size_t)16 * Bn * Tn];
__device__ float g_invcol[Bn * Tn];
__device__ float g_rowsum[Bn * Tn];
__device__ float g_wx[Bn * Tn];
__device__ float g_oa[Bn * Cn * Tn];
__device__ float g_h1[Bn * Cn * Tn];
__device__ float g_ws1[3 * Cn * Cn];             // weight-normed, split [r][c][o]
__device__ float g_ws2[3 * Cn * Cn];

// ---------------- weight norm -> split per-tap transposed layout -----------
__global__ __launch_bounds__(256) void wnorm_kernel(const float* __restrict__ v,
                                                    const float* __restrict__ g,
                                                    int which) {
    float* w = which ? g_ws2 : g_ws1;
    int o = blockIdx.x;
    int tid = threadIdx.x;
    __shared__ float red[256];
    float s = 0.f;
    for (int i = tid; i < Cn * 3; i += 256) {
        float t = v[o * Cn * 3 + i];
        s += t * t;
    }
    red[tid] = s;
    __syncthreads();
    for (int st = 128; st > 0; st >>= 1) {
        if (tid < st) red[tid] += red[tid + st];
        __syncthreads();
    }
    float scale = g[o] * rsqrtf(red[0]);
    for (int i = tid; i < Cn * 3; i += 256) {
        int c = i / 3, r = i - c * 3;
        w[(r * Cn + c) * Cn + o] = v[o * Cn * 3 + i] * scale;
    }
}

// helper: convert fragment floats to tf32
template <typename FragT>
__device__ __forceinline__ void to_tf32(FragT& f) {
#pragma unroll
    for (int i = 0; i < f.num_elements; i++) f.x[i] = wmma::__float_to_tf32(f.x[i]);
}

// ------- fused q/k/v projection (tf32 wmma) --------------------------------
// blockIdx.y: 0-3 -> q, 4-7 -> k, 8-11 -> v.  out[n,t] = sum_c W[c,n]x[b,c,t]
__global__ __launch_bounds__(256) void gemm_qkv_wmma(
        const float* __restrict__ x,
        const float* __restrict__ Wq, const float* __restrict__ bq,
        const float* __restrict__ Wk, const float* __restrict__ bk,
        const float* __restrict__ Wv, const float* __restrict__ bv) {
    int b = blockIdx.z;
    int t0 = blockIdx.x * 64;
    int by = blockIdx.y;
    int which = by >> 2;               // 0=q 1=k 2=v
    int n0 = (by & 3) * 64;
    const float* W = (which == 0) ? Wq : (which == 1) ? Wk : Wv;
    const float* bias = (which == 0) ? bq : (which == 1) ? bk : bv;
    int ldW = 256;                     // KEYn == Cn == 256
    int tid = threadIdx.x;
    __shared__ float Ws[16][72];       // [c][n]
    __shared__ float Xs[16][72];       // [c][t]
    __shared__ float Ss[64][72];
    int wid = tid >> 5;
    int m_off = (wid & 3) * 16;        // n
    int n_base = (wid >> 2) * 32;      // t
    wmma::fragment<wmma::accumulator, 16, 16, 8, float> acc[2];
    wmma::fill_fragment(acc[0], 0.f);
    wmma::fill_fragment(acc[1], 0.f);
    const float* xb = x + (size_t)b * Cn * Tn;
    int lr = tid >> 4, lc = (tid & 15) * 4;
    for (int c0 = 0; c0 < Cn; c0 += 16) {
        *(float4*)&Ws[lr][lc] = *(const float4*)&W[(c0 + lr) * ldW + n0 + lc];
        *(float4*)&Xs[lr][lc] = *(const float4*)&xb[(size_t)(c0 + lr) * Tn + t0 + lc];
        __syncthreads();
#pragma unroll
        for (int ks = 0; ks < 16; ks += 8) {
            wmma::fragment<wmma::matrix_a, 16, 16, 8, wmma::precision::tf32, wmma::col_major> a;
            wmma::load_matrix_sync(a, &Ws[ks][m_off], 72);
            to_tf32(a);
#pragma unroll
            for (int nf = 0; nf < 2; nf++) {
                wmma::fragment<wmma::matrix_b, 16, 16, 8, wmma::precision::tf32, wmma::row_major> bf;
                wmma::load_matrix_sync(bf, &Xs[ks][n_base + nf * 16], 72);
                to_tf32(bf);
                wmma::mma_sync(acc[nf], a, bf, acc[nf]);
            }
        }
        __syncthreads();
    }
    wmma::store_matrix_sync(&Ss[m_off][n_base], acc[0], 72, wmma::mem_row_major);
    wmma::store_matrix_sync(&Ss[m_off][n_base + 16], acc[1], 72, wmma::mem_row_major);
    __syncthreads();
    if (which < 2) {   // q/k: channel-major [n][t]
        float* out = (which == 0) ? g_q : g_k;
        int row = tid >> 2, colb = (tid & 3) * 16;
        int n = n0 + row;
        float bo = bias[n];
        float* orow = &out[((size_t)b * KEYn + n) * Tn + t0 + colb];
#pragma unroll
        for (int q = 0; q < 4; q++) {
            float4 res;
            res.x = Ss[row][colb + q * 4 + 0] + bo;
            res.y = Ss[row][colb + q * 4 + 1] + bo;
            res.z = Ss[row][colb + q * 4 + 2] + bo;
            res.w = Ss[row][colb + q * 4 + 3] + bo;
            *(float4*)&orow[q * 4] = res;
        }
    } else {           // v: token-major [t][c], transposed write via smem
        int col = tid >> 2;            // t index 0..63
        int rowb = (tid & 3) * 16;     // n chunk
#pragma unroll
        for (int q = 0; q < 4; q++) {
            float4 res;
            res.x = Ss[rowb + q * 4 + 0][col] + bias[n0 + rowb + q * 4 + 0];
            res.y = Ss[rowb + q * 4 + 1][col] + bias[n0 + rowb + q * 4 + 1];
            res.z = Ss[rowb + q * 4 + 2][col] + bias[n0 + rowb + q * 4 + 2];
            res.w = Ss[rowb + q * 4 + 3][col] + bias[n0 + rowb + q * 4 + 3];
            *(float4*)&g_v[((size_t)b * Tn + t0 + col) * Cn + n0 + rowb + q * 4] = res;
        }
    }
}

// ------- scores (tf32 wmma): e[b,j,i] = (i<=j)?exp(q_j·k_i/16):0 + colparts -
__global__ __launch_bounds__(256) void gemm_scores() {
    int b = blockIdx.z;
    int i0 = blockIdx.x * 64, j0 = blockIdx.y * 64;
    int tid = threadIdx.x;
    float* S = g_attn + (size_t)b * Tn * Tn;
    float* cpart = g_colpart + (size_t)(j0 >> 6) * Bn * Tn + b * Tn + i0;
    int c = tid & 63, rb = tid >> 6;
    if (i0 > j0) {  // fully masked
#pragma unroll
        for (int rr = 0; rr < 16; rr++)
            S[(size_t)(j0 + rb * 16 + rr) * Tn + i0 + c] = 0.f;
        if (tid < 64) cpart[tid] = 0.f;
        return;
    }
    __shared__ float Qs[16][72];   // [key][j]
    __shared__ float Ks[16][72];   // [key][i]
    __shared__ float Ss[64][72];
    __shared__ float cred[4][64];
    int wid = tid >> 5;
    int m_off = (wid & 3) * 16;
    int n_base = (wid >> 2) * 32;
    const float* qb = g_q + (size_t)b * KEYn * Tn;
    const float* kb = g_k + (size_t)b * KEYn * Tn;
    wmma::fragment<wmma::accumulator, 16, 16, 8, float> acc[2];
    wmma::fill_fragment(acc[0], 0.f);
    wmma::fill_fragment(acc[1], 0.f);
    int lr = tid >> 4, lc = (tid & 15) * 4;
    for (int kc = 0; kc < KEYn; kc += 16) {
        *(float4*)&Qs[lr][lc] = *(const float4*)&qb[(size_t)(kc + lr) * Tn + j0 + lc];
        *(float4*)&Ks[lr][lc] = *(const float4*)&kb[(size_t)(kc + lr) * Tn + i0 + lc];
        __syncthreads();
#pragma unroll
        for (int ks = 0; ks < 16; ks += 8) {
            wmma::fragment<wmma::matrix_a, 16, 16, 8, wmma::precision::tf32, wmma::col_major> a;
            wmma::load_matrix_sync(a, &Qs[ks][m_off], 72);
            to_tf32(a);
#pragma unroll
            for (int nf = 0; nf < 2; nf++) {
                wmma::fragment<wmma::matrix_b, 16, 16, 8, wmma::precision::tf32, wmma::row_major> bf;
                wmma::load_matrix_sync(bf, &Ks[ks][n_base + nf * 16], 72);
                to_tf32(bf);
                wmma::mma_sync(acc[nf], a, bf, acc[nf]);
            }
        }
        __syncthreads();
    }
    wmma::store_matrix_sync(&Ss[m_off][n_base], acc[0], 72, wmma::mem_row_major);
    wmma::store_matrix_sync(&Ss[m_off][n_base + 16], acc[1], 72, wmma::mem_row_major);
    __syncthreads();
    float csum = 0.f;
#pragma unroll
    for (int rr = 0; rr < 16; rr++) {
        int row = rb * 16 + rr;
        int j = j0 + row, i = i0 + c;
        float e = (i <= j) ? __expf(Ss[row][c] * INV_SQRT_K) : 0.f;
        S[(size_t)j * Tn + i] = e;
        csum += e;
    }
    cred[rb][c] = csum;
    __syncthreads();
    if (tid < 64) {
        float s = cred[0][tid] + cred[1][tid] + cred[2][tid] + cred[3][tid];
        cpart[tid] = s;
    }
}

// ------- invcol[b,i] = 1 / sum_p colpart[p][b,i] ---------------------------
__global__ __launch_bounds__(256) void invcol_kernel() {
    int idx = blockIdx.x * 256 + threadIdx.x;
    float s = 0.f;
#pragma unroll
    for (int p = 0; p < 16; p++) s += g_colpart[(size_t)p * Bn * Tn + idx];
    g_invcol[idx] = 1.f / s;
}

// ------- rowsum[b,j] = sum_i e[b,j,i] * invcol[b,i] ------------------------
__global__ __launch_bounds__(256) void row_sum() {
    int b = blockIdx.y;
    int j = blockIdx.x * 8 + (threadIdx.x >> 5);
    int lane = threadIdx.x & 31;
    const float* row = g_attn + (size_t)b * Tn * Tn + (size_t)j * Tn;
    const float* inv = g_invcol + b * Tn;
    float s = 0.f;
    for (int i = lane; i < Tn; i += 32) s += row[i] * inv[i];
#pragma unroll
    for (int o = 16; o > 0; o >>= 1) s += __shfl_xor_sync(0xffffffffu, s, o);
    if (lane == 0) g_rowsum[b * Tn + j] = s;
}

// ------- weight_x[b,:] = softmax_j(rowsum[b,:]) ----------------------------
__global__ __launch_bounds__(256) void wx_softmax() {
    int b = blockIdx.x;
    int tid = threadIdx.x;
    __shared__ float red[256];
    const float* r = g_rowsum + b * Tn;
    float m = -1e30f;
    for (int j = tid; j < Tn; j += 256) m = fmaxf(m, r[j]);
    red[tid] = m;
    __syncthreads();
    for (int st = 128; st > 0; st >>= 1) {
        if (tid < st) red[tid] = fmaxf(red[tid], red[tid + st]);
        __syncthreads();
    }
    m = red[0];
    __syncthreads();
    float sum = 0.f;
    for (int j = tid; j < Tn; j += 256) sum += __expf(r[j] - m);
    red[tid] = sum;
    __syncthreads();
    for (int st = 128; st > 0; st >>= 1) {
        if (tid < st) red[tid] += red[tid + st];
        __syncthreads();
    }
    float inv = 1.f / red[0];
    for (int j = tid; j < Tn; j += 256)
        g_wx[b * Tn + j] = __expf(r[j] - m) * inv;
}

// ------- attn·V (tf32 wmma): oa[b,c,j] = sum_i e[j,i]*invcol[i]*v[i,c] -----
__global__ __launch_bounds__(256) void gemm_av() {
    int b = blockIdx.z;
    int j0 = blockIdx.x * 64, c0 = blockIdx.y * 64;
    int tid = threadIdx.x;
    __shared__ float As[16][72];   // [i][c] scaled v
    __shared__ float Es[64][24];   // [j][i-chunk]
    const float* A = g_attn + (size_t)b * Tn * Tn;
    const float* V = g_v + (size_t)b * Tn * Cn;
    const float* inv = g_invcol + b * Tn;
    int wid = tid >> 5;
    int m_off = (wid & 3) * 16;          // c
    int n_base = (wid >> 2) * 32;        // j
    wmma::fragment<wmma::accumulator, 16, 16, 8, float> acc[2];
    wmma::fill_fragment(acc[0], 0.f);
    wmma::fill_fragment(acc[1], 0.f);
    int ar = tid >> 4, ac = (tid & 15) * 4;
    int er = tid >> 2, ec = (tid & 3) * 4;
    int kend = j0 + 64;
    for (int ii = 0; ii < kend; ii += 16) {
        float sc = inv[ii + ar];
        float4 v4 = *(const float4*)&V[(size_t)(ii + ar) * Cn + c0 + ac];
        *(float4*)&As[ar][ac] = make_float4(v4.x * sc, v4.y * sc, v4.z * sc, v4.w * sc);
        *(float4*)&Es[er][ec] = *(const float4*)&A[(size_t)(j0 + er) * Tn + ii + ec];
        __syncthreads();
#pragma unroll
        for (int ks = 0; ks < 16; ks += 8) {
            wmma::fragment<wmma::matrix_a, 16, 16, 8, wmma::precision::tf32, wmma::col_major> a;
            wmma::load_matrix_sync(a, &As[ks][m_off], 72);
            to_tf32(a);
#pragma unroll
            for (int nf = 0; nf < 2; nf++) {
                wmma::fragment<wmma::matrix_b, 16, 16, 8, wmma::precision::tf32, wmma::col_major> bf;
                wmma::load_matrix_sync(bf, &Es[n_base + nf * 16][ks], 24);
                to_tf32(bf);
                wmma::mma_sync(acc[nf], a, bf, acc[nf]);
            }
        }
        __syncthreads();
    }
    float* obase = &g_oa[((size_t)b * Cn + c0 + m_off) * Tn + j0];
    wmma::store_matrix_sync(obase + n_base, acc[0], Tn, wmma::mem_row_major);
    wmma::store_matrix_sync(obase + n_base + 16, acc[1], Tn, wmma::mem_row_major);
}

// ------- causal conv (tf32 wmma implicit GEMM, KS=3) + fusion --------------
template <int WHICH>
__global__ __launch_bounds__(256) void conv_kernel(const float* __restrict__ bias,
                                                   const float* __restrict__ x,
                                                   float* __restrict__ out_final) {
    const float* in = (WHICH == 1) ? g_oa : g_h1;
    const float* w  = (WHICH == 1) ? g_ws1 : g_ws2;
    float* out = (WHICH == 1) ? g_h1 : out_final;
    int b = blockIdx.z;
    int t0 = blockIdx.x * 64, o0 = blockIdx.y * 64;
    int tid = threadIdx.x;
    __shared__ float As[3][16][72];   // [r][c][o]
    __shared__ float In3[3][16][72];  // [r][c][t-window per tap]
    __shared__ float Ss[64][72];
    int wid = tid >> 5;
    int m_off = (wid & 3) * 16;       // o
    int n_base = (wid >> 2) * 32;     // t
    wmma::fragment<wmma::accumulator, 16, 16, 8, float> acc[2];
    wmma::fill_fragment(acc[0], 0.f);
    wmma::fill_fragment(acc[1], 0.f);
    const float* inb = in + (size_t)b * Cn * Tn;
    for (int cc0 = 0; cc0 < Cn; cc0 += 16) {
#pragma unroll
        for (int q = 0; q < 3; q++) {
            int lin = tid + q * 256;
            int row = lin >> 4, col = (lin & 15) * 4;
            int r = row >> 4, kk = row & 15;
            *(float4*)&As[r][kk][col] =
                *(const float4*)&w[((r * Cn) + cc0 + kk) * Cn + o0 + col];
        }
        // input windows via SCALAR loads (tap shift breaks float4 alignment)
#pragma unroll
        for (int q = 0; q < 12; q++) {
            int lin = tid + q * 256;          // 0..3071
            int r = lin >> 10;
            int rem = lin & 1023;
            int kk = rem >> 6, col = rem & 63;
            int gt = t0 + col - 2 + r;
            In3[r][kk][col] = (gt >= 0)
                ? inb[(size_t)(cc0 + kk) * Tn + gt] : 0.f;
        }
        __syncthreads();
#pragma unroll
        for (int r = 0; r < 3; r++) {
#pragma unroll
            for (int ks = 0; ks < 16; ks += 8) {
                wmma::fragment<wmma::matrix_a, 16, 16, 8, wmma::precision::tf32, wmma::col_major> a;
                wmma::load_matrix_sync(a, &As[r][ks][m_off], 72);
                to_tf32(a);
#pragma unroll
                for (int nf = 0; nf < 2; nf++) {
                    wmma::fragment<wmma::matrix_b, 16, 16, 8, wmma::precision::tf32, wmma::row_major> bf;
                    wmma::load_matrix_sync(bf, &In3[r][ks][n_base + nf * 16], 72);
                    to_tf32(bf);
                    wmma::mma_sync(acc[nf], a, bf, acc[nf]);
                }
            }
        }
        __syncthreads();
    }
    wmma::store_matrix_sync(&Ss[m_off][n_base], acc[0], 72, wmma::mem_row_major);
    wmma::store_matrix_sync(&Ss[m_off][n_base + 16], acc[1], 72, wmma::mem_row_major);
    __syncthreads();
    int row = tid >> 2, colb = (tid & 3) * 16;
    int o = o0 + row;
    float bo = bias[o];
    if (WHICH == 2) {
        const float* xrow = &x[((size_t)b * Cn + o) * Tn + t0 + colb];
        const float* wxp = &g_wx[b * Tn + t0 + colb];
        float* orow = &out[((size_t)b * Cn + o) * Tn + t0 + colb];
#pragma unroll
        for (int q = 0; q < 4; q++) {
            float4 xv = *(const float4*)&xrow[q * 4];
            float4 wx4 = *(const float4*)&wxp[q * 4];
            float4 res;
            float h0 = fmaxf(Ss[row][colb + q * 4 + 0] + bo, 0.f);
            float h1 = fmaxf(Ss[row][colb + q * 4 + 1] + bo, 0.f);
            float h2 = fmaxf(Ss[row][colb + q * 4 + 2] + bo, 0.f);
            float h3 = fmaxf(Ss[row][colb + q * 4 + 3] + bo, 0.f);
            res.x = fmaxf(h0 + xv.x + wx4.x * xv.x, 0.f);
            res.y = fmaxf(h1 + xv.y + wx4.y * xv.y, 0.f);
            res.z = fmaxf(h2 + xv.z + wx4.z * xv.z, 0.f);
            res.w = fmaxf(h3 + xv.w + wx4.w * xv.w, 0.f);
            *(float4*)&orow[q * 4] = res;
        }
    } else {
        float* orow = &out[((size_t)b * Cn + o) * Tn + t0 + colb];
#pragma unroll
        for (int q = 0; q < 4; q++) {
            float4 res;
            res.x = fmaxf(Ss[row][colb + q * 4 + 0] + bo, 0.f);
            res.y = fmaxf(Ss[row][colb + q * 4 + 1] + bo, 0.f);
            res.z = fmaxf(Ss[row][colb + q * 4 + 2] + bo, 0.f);
            res.w = fmaxf(Ss[row][colb + q * 4 + 3] + bo, 0.f);
            *(float4*)&orow[q * 4] = res;
        }
    }
}

// ---------------------------------------------------------------------------
extern "C" void kernel_launch(void* const* d_in, const int* in_sizes, int n_in,
                              void* d_out, int out_size) {
    const float* x   = (const float*)d_in[0];
    const float* Wq  = (const float*)d_in[1];
    const float* bq  = (const float*)d_in[2];
    const float* Wk  = (const float*)d_in[3];
    const float* bk  = (const float*)d_in[4];
    const float* Wv  = (const float*)d_in[5];
    const float* bv  = (const float*)d_in[6];
    const float* c1v = (const float*)d_in[7];
    const float* c1g = (const float*)d_in[8];
    const float* c1b = (const float*)d_in[9];
    const float* c2v = (const float*)d_in[10];
    const float* c2g = (const float*)d_in[11];
    const float* c2b = (const float*)d_in[12];
    float* out = (float*)d_out;

    wnorm_kernel<<<Cn, 256>>>(c1v, c1g, 0);
    wnorm_kernel<<<Cn, 256>>>(c2v, c2g, 1);

    gemm_qkv_wmma<<<dim3(Tn / 64, 12, Bn), 256>>>(x, Wq, bq, Wk, bk, Wv, bv);

    gemm_scores<<<dim3(Tn / 64, Tn / 64, Bn), 256>>>();
    invcol_kernel<<<(Bn * Tn) / 256, 256>>>();
    row_sum<<<dim3(Tn / 8, Bn), 256>>>();
    wx_softmax<<<Bn, 256>>>();
    gemm_av<<<dim3(Tn / 64, Cn / 64, Bn), 256>>>();

    conv_kernel<1><<<dim3(Tn / 64, Cn / 64, Bn), 256>>>(c1b, x, nullptr);
    conv_kernel<2><<<dim3(Tn / 64, Cn / 64, Bn), 256>>>(c2b, x, out);
}

// round 7
// speedup vs baseline: 1.7362x; 1.0378x over previous
#include <cuda_runtime.h>
#include <mma.h>
#include <cstdint>

using namespace nvcuda;

#define Bn   16
#define Cn   256
#define Tn   1024
#define KEYn 256
#define INV_SQRT_K 0.0625f

// ---------------- scratch (device globals; no allocation allowed) ----------
__device__ float g_q[Bn * KEYn * Tn];            // channel-major [B,KEY,T]
__device__ float g_k[Bn * KEYn * Tn];            // channel-major [B,KEY,T]
__device__ float g_v[Bn * Tn * Cn];              // token-major   [B,T,C]
__device__ float g_attn[(size_t)Bn * Tn * Tn];   // exp(scores); upper tiles unused
__device__ float g_colpart[(size_t)16 * Bn * Tn];
__device__ float g_invcol[Bn * Tn];
__device__ float g_rowsum[Bn * Tn];
__device__ float g_wx[Bn * Tn];
__device__ float g_oa[Bn * Cn * Tn];
__device__ float g_h1[Bn * Cn * Tn];
__device__ float g_ws1[3 * Cn * Cn];             // weight-normed, split [r][c][o]
__device__ float g_ws2[3 * Cn * Cn];

// ---------------- weight norm -> split per-tap transposed layout -----------
__global__ __launch_bounds__(256) void wnorm_kernel(const float* __restrict__ v,
                                                    const float* __restrict__ g,
                                                    int which) {
    float* w = which ? g_ws2 : g_ws1;
    int o = blockIdx.x;
    int tid = threadIdx.x;
    __shared__ float red[256];
    float s = 0.f;
    for (int i = tid; i < Cn * 3; i += 256) {
        float t = v[o * Cn * 3 + i];
        s += t * t;
    }
    red[tid] = s;
    __syncthreads();
    for (int st = 128; st > 0; st >>= 1) {
        if (tid < st) red[tid] += red[tid + st];
        __syncthreads();
    }
    float scale = g[o] * rsqrtf(red[0]);
    for (int i = tid; i < Cn * 3; i += 256) {
        int c = i / 3, r = i - c * 3;
        w[(r * Cn + c) * Cn + o] = v[o * Cn * 3 + i] * scale;
    }
}

// ------- fused q/k/v projection (tf32 wmma, truncation conversion) ---------
// blockIdx.y: 0-3 -> q, 4-7 -> k, 8-11 -> v.  out[n,t] = sum_c W[c,n]x[b,c,t]
__global__ __launch_bounds__(256) void gemm_qkv_wmma(
        const float* __restrict__ x,
        const float* __restrict__ Wq, const float* __restrict__ bq,
        const float* __restrict__ Wk, const float* __restrict__ bk,
        const float* __restrict__ Wv, const float* __restrict__ bv) {
    int b = blockIdx.z;
    int t0 = blockIdx.x * 64;
    int by = blockIdx.y;
    int which = by >> 2;               // 0=q 1=k 2=v
    int n0 = (by & 3) * 64;
    const float* W = (which == 0) ? Wq : (which == 1) ? Wk : Wv;
    const float* bias = (which == 0) ? bq : (which == 1) ? bk : bv;
    int tid = threadIdx.x;
    __shared__ float Ws[16][72];       // [c][n]
    __shared__ float Xs[16][72];       // [c][t]
    __shared__ float Ss[64][72];
    int wid = tid >> 5;
    int m_off = (wid & 3) * 16;        // n
    int n_base = (wid >> 2) * 32;      // t
    wmma::fragment<wmma::accumulator, 16, 16, 8, float> acc[2];
    wmma::fill_fragment(acc[0], 0.f);
    wmma::fill_fragment(acc[1], 0.f);
    const float* xb = x + (size_t)b * Cn * Tn;
    int lr = tid >> 4, lc = (tid & 15) * 4;
    for (int c0 = 0; c0 < Cn; c0 += 16) {
        *(float4*)&Ws[lr][lc] = *(const float4*)&W[(c0 + lr) * 256 + n0 + lc];
        *(float4*)&Xs[lr][lc] = *(const float4*)&xb[(size_t)(c0 + lr) * Tn + t0 + lc];
        __syncthreads();
#pragma unroll
        for (int ks = 0; ks < 16; ks += 8) {
            wmma::fragment<wmma::matrix_a, 16, 16, 8, wmma::precision::tf32, wmma::col_major> a;
            wmma::load_matrix_sync(a, &Ws[ks][m_off], 72);
#pragma unroll
            for (int nf = 0; nf < 2; nf++) {
                wmma::fragment<wmma::matrix_b, 16, 16, 8, wmma::precision::tf32, wmma::row_major> bf;
                wmma::load_matrix_sync(bf, &Xs[ks][n_base + nf * 16], 72);
                wmma::mma_sync(acc[nf], a, bf, acc[nf]);
            }
        }
        __syncthreads();
    }
    wmma::store_matrix_sync(&Ss[m_off][n_base], acc[0], 72, wmma::mem_row_major);
    wmma::store_matrix_sync(&Ss[m_off][n_base + 16], acc[1], 72, wmma::mem_row_major);
    __syncthreads();
    if (which < 2) {   // q/k: channel-major [n][t]
        float* out = (which == 0) ? g_q : g_k;
        int row = tid >> 2, colb = (tid & 3) * 16;
        int n = n0 + row;
        float bo = bias[n];
        float* orow = &out[((size_t)b * KEYn + n) * Tn + t0 + colb];
#pragma unroll
        for (int q = 0; q < 4; q++) {
            float4 res;
            res.x = Ss[row][colb + q * 4 + 0] + bo;
            res.y = Ss[row][colb + q * 4 + 1] + bo;
            res.z = Ss[row][colb + q * 4 + 2] + bo;
            res.w = Ss[row][colb + q * 4 + 3] + bo;
            *(float4*)&orow[q * 4] = res;
        }
    } else {           // v: token-major [t][c], transposed write via smem
        int col = tid >> 2;            // t index 0..63
        int rowb = (tid & 3) * 16;     // n chunk
#pragma unroll
        for (int q = 0; q < 4; q++) {
            float4 res;
            res.x = Ss[rowb + q * 4 + 0][col] + bias[n0 + rowb + q * 4 + 0];
            res.y = Ss[rowb + q * 4 + 1][col] + bias[n0 + rowb + q * 4 + 1];
            res.z = Ss[rowb + q * 4 + 2][col] + bias[n0 + rowb + q * 4 + 2];
            res.w = Ss[rowb + q * 4 + 3][col] + bias[n0 + rowb + q * 4 + 3];
            *(float4*)&g_v[((size_t)b * Tn + t0 + col) * Cn + n0 + rowb + q * 4] = res;
        }
    }
}

// ------- scores (tf32 wmma, triangular grid): only tiles with i0 <= j0 -----
__global__ __launch_bounds__(256) void gemm_scores() {
    int b = blockIdx.z;
    // decode linear lower-triangle index -> (it, jt), it <= jt
    int idx = blockIdx.x;
    int jt = (int)((sqrtf(8.f * idx + 1.f) - 1.f) * 0.5f);
    while ((jt + 1) * (jt + 2) / 2 <= idx) jt++;
    while (jt * (jt + 1) / 2 > idx) jt--;
    int it = idx - jt * (jt + 1) / 2;
    int i0 = it * 64, j0 = jt * 64;
    int tid = threadIdx.x;
    float* S = g_attn + (size_t)b * Tn * Tn;
    float* cpart = g_colpart + (size_t)jt * Bn * Tn + b * Tn + i0;
    int c = tid & 63, rb = tid >> 6;
    __shared__ float Qs[16][72];   // [key][j]
    __shared__ float Ks[16][72];   // [key][i]
    __shared__ float Ss[64][72];
    __shared__ float cred[4][64];
    int wid = tid >> 5;
    int m_off = (wid & 3) * 16;
    int n_base = (wid >> 2) * 32;
    const float* qb = g_q + (size_t)b * KEYn * Tn;
    const float* kb = g_k + (size_t)b * KEYn * Tn;
    wmma::fragment<wmma::accumulator, 16, 16, 8, float> acc[2];
    wmma::fill_fragment(acc[0], 0.f);
    wmma::fill_fragment(acc[1], 0.f);
    int lr = tid >> 4, lc = (tid & 15) * 4;
    for (int kc = 0; kc < KEYn; kc += 16) {
        *(float4*)&Qs[lr][lc] = *(const float4*)&qb[(size_t)(kc + lr) * Tn + j0 + lc];
        *(float4*)&Ks[lr][lc] = *(const float4*)&kb[(size_t)(kc + lr) * Tn + i0 + lc];
        __syncthreads();
#pragma unroll
        for (int ks = 0; ks < 16; ks += 8) {
            wmma::fragment<wmma::matrix_a, 16, 16, 8, wmma::precision::tf32, wmma::col_major> a;
            wmma::load_matrix_sync(a, &Qs[ks][m_off], 72);
#pragma unroll
            for (int nf = 0; nf < 2; nf++) {
                wmma::fragment<wmma::matrix_b, 16, 16, 8, wmma::precision::tf32, wmma::row_major> bf;
                wmma::load_matrix_sync(bf, &Ks[ks][n_base + nf * 16], 72);
                wmma::mma_sync(acc[nf], a, bf, acc[nf]);
            }
        }
        __syncthreads();
    }
    wmma::store_matrix_sync(&Ss[m_off][n_base], acc[0], 72, wmma::mem_row_major);
    wmma::store_matrix_sync(&Ss[m_off][n_base + 16], acc[1], 72, wmma::mem_row_major);
    __syncthreads();
    float csum = 0.f;
#pragma unroll
    for (int rr = 0; rr < 16; rr++) {
        int row = rb * 16 + rr;
        int j = j0 + row, i = i0 + c;
        float e = (i <= j) ? __expf(Ss[row][c] * INV_SQRT_K) : 0.f;
        S[(size_t)j * Tn + i] = e;
        csum += e;
    }
    cred[rb][c] = csum;
    __syncthreads();
    if (tid < 64) {
        float s = cred[0][tid] + cred[1][tid] + cred[2][tid] + cred[3][tid];
        cpart[tid] = s;
    }
}

// ------- invcol[b,i] = 1 / sum_{p >= i_tile} colpart[p][b,i] ---------------
__global__ __launch_bounds__(256) void invcol_kernel() {
    int idx = blockIdx.x * 256 + threadIdx.x;
    int i = idx & (Tn - 1);
    int p0 = i >> 6;
    float s = 0.f;
    for (int p = p0; p < 16; p++) s += g_colpart[(size_t)p * Bn * Tn + idx];
    g_invcol[idx] = 1.f / s;
}

// ------- rowsum[b,j] = sum_{i<=j} e[b,j,i] * invcol[b,i] -------------------
__global__ __launch_bounds__(256) void row_sum() {
    int b = blockIdx.y;
    int j = blockIdx.x * 8 + (threadIdx.x >> 5);
    int lane = threadIdx.x & 31;
    const float* row = g_attn + (size_t)b * Tn * Tn + (size_t)j * Tn;
    const float* inv = g_invcol + b * Tn;
    float s = 0.f;
    for (int i = lane; i <= j; i += 32) s += row[i] * inv[i];
#pragma unroll
    for (int o = 16; o > 0; o >>= 1) s += __shfl_xor_sync(0xffffffffu, s, o);
    if (lane == 0) g_rowsum[b * Tn + j] = s;
}

// ------- weight_x[b,:] = softmax_j(rowsum[b,:]) ----------------------------
__global__ __launch_bounds__(256) void wx_softmax() {
    int b = blockIdx.x;
    int tid = threadIdx.x;
    __shared__ float red[256];
    const float* r = g_rowsum + b * Tn;
    float m = -1e30f;
    for (int j = tid; j < Tn; j += 256) m = fmaxf(m, r[j]);
    red[tid] = m;
    __syncthreads();
    for (int st = 128; st > 0; st >>= 1) {
        if (tid < st) red[tid] = fmaxf(red[tid], red[tid + st]);
        __syncthreads();
    }
    m = red[0];
    __syncthreads();
    float sum = 0.f;
    for (int j = tid; j < Tn; j += 256) sum += __expf(r[j] - m);
    red[tid] = sum;
    __syncthreads();
    for (int st = 128; st > 0; st >>= 1) {
        if (tid < st) red[tid] += red[tid + st];
        __syncthreads();
    }
    float inv = 1.f / red[0];
    for (int j = tid; j < Tn; j += 256)
        g_wx[b * Tn + j] = __expf(r[j] - m) * inv;
}

// ------- attn·V (tf32 wmma): oa[b,c,j] = sum_i e[j,i]*invcol[i]*v[i,c] -----
__global__ __launch_bounds__(256) void gemm_av() {
    int b = blockIdx.z;
    int j0 = blockIdx.x * 64, c0 = blockIdx.y * 64;
    int tid = threadIdx.x;
    __shared__ float As[16][72];   // [i][c] scaled v
    __shared__ float Es[64][24];   // [j][i-chunk]
    const float* A = g_attn + (size_t)b * Tn * Tn;
    const float* V = g_v + (size_t)b * Tn * Cn;
    const float* inv = g_invcol + b * Tn;
    int wid = tid >> 5;
    int m_off = (wid & 3) * 16;          // c
    int n_base = (wid >> 2) * 32;        // j
    wmma::fragment<wmma::accumulator, 16, 16, 8, float> acc[2];
    wmma::fill_fragment(acc[0], 0.f);
    wmma::fill_fragment(acc[1], 0.f);
    int ar = tid >> 4, ac = (tid & 15) * 4;
    int er = tid >> 2, ec = (tid & 3) * 4;
    int kend = j0 + 64;
    for (int ii = 0; ii < kend; ii += 16) {
        float sc = inv[ii + ar];
        float4 v4 = *(const float4*)&V[(size_t)(ii + ar) * Cn + c0 + ac];
        *(float4*)&As[ar][ac] = make_float4(v4.x * sc, v4.y * sc, v4.z * sc, v4.w * sc);
        *(float4*)&Es[er][ec] = *(const float4*)&A[(size_t)(j0 + er) * Tn + ii + ec];
        __syncthreads();
#pragma unroll
        for (int ks = 0; ks < 16; ks += 8) {
            wmma::fragment<wmma::matrix_a, 16, 16, 8, wmma::precision::tf32, wmma::col_major> a;
            wmma::load_matrix_sync(a, &As[ks][m_off], 72);
#pragma unroll
            for (int nf = 0; nf < 2; nf++) {
                wmma::fragment<wmma::matrix_b, 16, 16, 8, wmma::precision::tf32, wmma::col_major> bf;
                wmma::load_matrix_sync(bf, &Es[n_base + nf * 16][ks], 24);
                wmma::mma_sync(acc[nf], a, bf, acc[nf]);
            }
        }
        __syncthreads();
    }
    float* obase = &g_oa[((size_t)b * Cn + c0 + m_off) * Tn + j0];
    wmma::store_matrix_sync(obase + n_base, acc[0], Tn, wmma::mem_row_major);
    wmma::store_matrix_sync(obase + n_base + 16, acc[1], Tn, wmma::mem_row_major);
}

// ------- causal conv (tf32 wmma implicit GEMM, KS=3) + fusion --------------
template <int WHICH>
__global__ __launch_bounds__(256) void conv_kernel(const float* __restrict__ bias,
                                                   const float* __restrict__ x,
                                                   float* __restrict__ out_final) {
    const float* in = (WHICH == 1) ? g_oa : g_h1;
    const float* w  = (WHICH == 1) ? g_ws1 : g_ws2;
    float* out = (WHICH == 1) ? g_h1 : out_final;
    int b = blockIdx.z;
    int t0 = blockIdx.x * 64, o0 = blockIdx.y * 64;
    int tid = threadIdx.x;
    __shared__ float As[3][16][72];   // [r][c][o]
    __shared__ float In3[3][16][72];  // [r][c][t-window per tap]
    __shared__ float Ss[64][72];
    int wid = tid >> 5;
    int m_off = (wid & 3) * 16;       // o
    int n_base = (wid >> 2) * 32;     // t
    wmma::fragment<wmma::accumulator, 16, 16, 8, float> acc[2];
    wmma::fill_fragment(acc[0], 0.f);
    wmma::fill_fragment(acc[1], 0.f);
    const float* inb = in + (size_t)b * Cn * Tn;
    for (int cc0 = 0; cc0 < Cn; cc0 += 16) {
#pragma unroll
        for (int q = 0; q < 3; q++) {
            int lin = tid + q * 256;
            int row = lin >> 4, col = (lin & 15) * 4;
            int r = row >> 4, kk = row & 15;
            *(float4*)&As[r][kk][col] =
                *(const float4*)&w[((r * Cn) + cc0 + kk) * Cn + o0 + col];
        }
        // input windows via SCALAR loads (tap shift breaks float4 alignment)
#pragma unroll
        for (int q = 0; q < 12; q++) {
            int lin = tid + q * 256;          // 0..3071
            int r = lin >> 10;
            int rem = lin & 1023;
            int kk = rem >> 6, col = rem & 63;
            int gt = t0 + col - 2 + r;
            In3[r][kk][col] = (gt >= 0)
                ? inb[(size_t)(cc0 + kk) * Tn + gt] : 0.f;
        }
        __syncthreads();
#pragma unroll
        for (int r = 0; r < 3; r++) {
#pragma unroll
            for (int ks = 0; ks < 16; ks += 8) {
                wmma::fragment<wmma::matrix_a, 16, 16, 8, wmma::precision::tf32, wmma::col_major> a;
                wmma::load_matrix_sync(a, &As[r][ks][m_off], 72);
#pragma unroll
                for (int nf = 0; nf < 2; nf++) {
                    wmma::fragment<wmma::matrix_b, 16, 16, 8, wmma::precision::tf32, wmma::row_major> bf;
                    wmma::load_matrix_sync(bf, &In3[r][ks][n_base + nf * 16], 72);
                    wmma::mma_sync(acc[nf], a, bf, acc[nf]);
                }
            }
        }
        __syncthreads();
    }
    wmma::store_matrix_sync(&Ss[m_off][n_base], acc[0], 72, wmma::mem_row_major);
    wmma::store_matrix_sync(&Ss[m_off][n_base + 16], acc[1], 72, wmma::mem_row_major);
    __syncthreads();
    int row = tid >> 2, colb = (tid & 3) * 16;
    int o = o0 + row;
    float bo = bias[o];
    if (WHICH == 2) {
        const float* xrow = &x[((size_t)b * Cn + o) * Tn + t0 + colb];
        const float* wxp = &g_wx[b * Tn + t0 + colb];
        float* orow = &out[((size_t)b * Cn + o) * Tn + t0 + colb];
#pragma unroll
        for (int q = 0; q < 4; q++) {
            float4 xv = *(const float4*)&xrow[q * 4];
            float4 wx4 = *(const float4*)&wxp[q * 4];
            float4 res;
            float h0 = fmaxf(Ss[row][colb + q * 4 + 0] + bo, 0.f);
            float h1 = fmaxf(Ss[row][colb + q * 4 + 1] + bo, 0.f);
            float h2 = fmaxf(Ss[row][colb + q * 4 + 2] + bo, 0.f);
            float h3 = fmaxf(Ss[row][colb + q * 4 + 3] + bo, 0.f);
            res.x = fmaxf(h0 + xv.x + wx4.x * xv.x, 0.f);
            res.y = fmaxf(h1 + xv.y + wx4.y * xv.y, 0.f);
            res.z = fmaxf(h2 + xv.z + wx4.z * xv.z, 0.f);
            res.w = fmaxf(h3 + xv.w + wx4.w * xv.w, 0.f);
            *(float4*)&orow[q * 4] = res;
        }
    } else {
        float* orow = &out[((size_t)b * Cn + o) * Tn + t0 + colb];
#pragma unroll
        for (int q = 0; q < 4; q++) {
            float4 res;
            res.x = fmaxf(Ss[row][colb + q * 4 + 0] + bo, 0.f);
            res.y = fmaxf(Ss[row][colb + q * 4 + 1] + bo, 0.f);
            res.z = fmaxf(Ss[row][colb + q * 4 + 2] + bo, 0.f);
            res.w = fmaxf(Ss[row][colb + q * 4 + 3] + bo, 0.f);
            *(float4*)&orow[q * 4] = res;
        }
    }
}

// ---------------------------------------------------------------------------
extern "C" void kernel_launch(void* const* d_in, const int* in_sizes, int n_in,
                              void* d_out, int out_size) {
    const float* x   = (const float*)d_in[0];
    const float* Wq  = (const float*)d_in[1];
    const float* bq  = (const float*)d_in[2];
    const float* Wk  = (const float*)d_in[3];
    const float* bk  = (const float*)d_in[4];
    const float* Wv  = (const float*)d_in[5];
    const float* bv  = (const float*)d_in[6];
    const float* c1v = (const float*)d_in[7];
    const float* c1g = (const float*)d_in[8];
    const float* c1b = (const float*)d_in[9];
    const float* c2v = (const float*)d_in[10];
    const float* c2g = (const float*)d_in[11];
    const float* c2b = (const float*)d_in[12];
    float* out = (float*)d_out;

    wnorm_kernel<<<Cn, 256>>>(c1v, c1g, 0);
    wnorm_kernel<<<Cn, 256>>>(c2v, c2g, 1);

    gemm_qkv_wmma<<<dim3(Tn / 64, 12, Bn), 256>>>(x, Wq, bq, Wk, bk, Wv, bv);

    gemm_scores<<<dim3(136, 1, Bn), 256>>>();   // triangular tile grid
    invcol_kernel<<<(Bn * Tn) / 256, 256>>>();
    row_sum<<<dim3(Tn / 8, Bn), 256>>>();
    wx_softmax<<<Bn, 256>>>();
    gemm_av<<<dim3(Tn / 64, Cn / 64, Bn), 256>>>();

    conv_kernel<1><<<dim3(Tn / 64, Cn / 64, Bn), 256>>>(c1b, x, nullptr);
    conv_kernel<2><<<dim3(Tn / 64, Cn / 64, Bn), 256>>>(c2b, x, out);
}